// round 1
// baseline (speedup 1.0000x reference)
#include <cuda_runtime.h>

// Problem constants
#define BB 16
#define NN 4096
#define DD 6
#define SS 1024          // NUM_CENTERS
#define KK 32
#define ROWS (BB*SS*KK)  // 524288
#define NB12 2048        // blocks for layer1/layer2 (256 rows each)
#define NB3  (BB*SS)     // 16384 blocks for layer3 (one per center)
#define KNN_BPB 32       // knn blocks per batch

// ---------------- device scratch (no allocations allowed) ----------------
__device__ int   g_gidx[ROWS];                       // 2 MB
__device__ float g_x1[(size_t)ROWS*64];              // 128 MB
__device__ float g_x2[(size_t)ROWS*64];              // 128 MB
__device__ float g_part1[NB12*128];                  // [blk][sum64|sq64]
__device__ float g_part2[NB12*128];
__device__ float g_part3[(size_t)NB3*256];           // [blk][sum128|sq128]
__device__ float g_max3[(size_t)BB*SS*128];
__device__ float g_min3[(size_t)BB*SS*128];
__device__ float g_s1[64], g_bb1[64], g_s2[64], g_bb2[64], g_s3[128], g_bb3[128];

// =========================================================================
// FPS: one block per batch. 512 threads x 8 points in registers.
// Matches reference: centers[0]=0; t=1..1023: idx=argmax(dmin) (first-max
// tie-break), dmin = min(dmin, ||p - c_idx||^2) with non-fused fp32.
// =========================================================================
__global__ void __launch_bounds__(512) fps_kernel(const float* __restrict__ xyz,
                                                  float* __restrict__ out_cxyz)
{
    const int b   = blockIdx.x;
    const int tid = threadIdx.x;
    const float* bx = xyz + (size_t)b * NN * 3;

    float px[8], py[8], pz[8], dmin[8];
    #pragma unroll
    for (int i = 0; i < 8; i++) {
        int j = tid * 8 + i;
        px[i] = bx[j*3+0]; py[i] = bx[j*3+1]; pz[i] = bx[j*3+2];
    }
    // init: distance to point 0
    float c0x = __ldg(&bx[0]), c0y = __ldg(&bx[1]), c0z = __ldg(&bx[2]);
    #pragma unroll
    for (int i = 0; i < 8; i++) {
        float dx = __fsub_rn(px[i], c0x);
        float dy = __fsub_rn(py[i], c0y);
        float dz = __fsub_rn(pz[i], c0z);
        dmin[i] = __fadd_rn(__fadd_rn(__fmul_rn(dx,dx), __fmul_rn(dy,dy)), __fmul_rn(dz,dz));
    }
    if (tid == 0) {
        out_cxyz[(size_t)b*SS*3 + 0] = c0x;
        out_cxyz[(size_t)b*SS*3 + 1] = c0y;
        out_cxyz[(size_t)b*SS*3 + 2] = c0z;
    }

    __shared__ unsigned long long s_warp[16];
    __shared__ unsigned long long s_win;
    const int lane = tid & 31, warp = tid >> 5;

    for (int t = 1; t < SS; t++) {
        // local argmax (key = d_bits<<32 | (0xFFFFFFFF - idx): max key => max d, ties -> min idx)
        unsigned long long best = 0ULL;
        #pragma unroll
        for (int i = 0; i < 8; i++) {
            unsigned long long k = ((unsigned long long)__float_as_uint(dmin[i]) << 32)
                                 | (unsigned)(0xFFFFFFFFu - (unsigned)(tid*8 + i));
            best = (k > best) ? k : best;
        }
        #pragma unroll
        for (int o = 16; o > 0; o >>= 1) {
            unsigned long long v = __shfl_xor_sync(0xFFFFFFFFu, best, o);
            best = (v > best) ? v : best;
        }
        if (lane == 0) s_warp[warp] = best;
        __syncthreads();
        if (warp == 0) {
            unsigned long long v = (lane < 16) ? s_warp[lane] : 0ULL;
            #pragma unroll
            for (int o = 16; o > 0; o >>= 1) {
                unsigned long long u = __shfl_xor_sync(0xFFFFFFFFu, v, o);
                v = (u > v) ? u : v;
            }
            if (lane == 0) s_win = v;
        }
        __syncthreads();
        int idx = (int)(0xFFFFFFFFu - (unsigned)(s_win & 0xFFFFFFFFULL));

        float cx = __ldg(&bx[idx*3+0]);
        float cy = __ldg(&bx[idx*3+1]);
        float cz = __ldg(&bx[idx*3+2]);
        if (tid == 0) {
            out_cxyz[((size_t)b*SS + t)*3 + 0] = cx;
            out_cxyz[((size_t)b*SS + t)*3 + 1] = cy;
            out_cxyz[((size_t)b*SS + t)*3 + 2] = cz;
        }
        #pragma unroll
        for (int i = 0; i < 8; i++) {
            float dx = __fsub_rn(px[i], cx);
            float dy = __fsub_rn(py[i], cy);
            float dz = __fsub_rn(pz[i], cz);
            float d = __fadd_rn(__fadd_rn(__fmul_rn(dx,dx), __fmul_rn(dy,dy)), __fmul_rn(dz,dz));
            dmin[i] = fminf(dmin[i], d);
        }
    }
}

// =========================================================================
// kNN: warp per center, streaming top-32 (1 slot/lane).
// d2 = max((ra+rb) - 2*dot, 0), non-fused, identical to reference.
// Lexicographic (d, idx) policy == jax.lax.top_k tie behavior.
// =========================================================================
__global__ void __launch_bounds__(256) knn_kernel(const float* __restrict__ xyz,
                                                  const float* __restrict__ cxyz)
{
    __shared__ float sx[NN], sy[NN], sz[NN];   // 48 KB
    const int b     = blockIdx.x >> 5;
    const int blkin = blockIdx.x & 31;
    const int tid   = threadIdx.x;
    const float* bx = xyz + (size_t)b * NN * 3;

    for (int j = tid; j < NN; j += 256) {
        sx[j] = bx[j*3+0]; sy[j] = bx[j*3+1]; sz[j] = bx[j*3+2];
    }
    __syncthreads();

    const int warp = tid >> 5, lane = tid & 31;
    const unsigned full = 0xFFFFFFFFu;

    for (int m = 0; m < 4; m++) {
        int s = (blkin * 8 + warp) * 4 + m;
        float ax = cxyz[((size_t)b*SS + s)*3 + 0];
        float ay = cxyz[((size_t)b*SS + s)*3 + 1];
        float az = cxyz[((size_t)b*SS + s)*3 + 2];
        float ra = __fadd_rn(__fadd_rn(__fmul_rn(ax,ax), __fmul_rn(ay,ay)), __fmul_rn(az,az));

        // init heap with points 0..31
        float hd; int hi;
        {
            int j = lane;
            float bxx = sx[j], byy = sy[j], bzz = sz[j];
            float rb  = __fadd_rn(__fadd_rn(__fmul_rn(bxx,bxx), __fmul_rn(byy,byy)), __fmul_rn(bzz,bzz));
            float dot = __fadd_rn(__fadd_rn(__fmul_rn(ax,bxx), __fmul_rn(ay,byy)), __fmul_rn(az,bzz));
            hd = fmaxf(__fsub_rn(__fadd_rn(ra, rb), __fmul_rn(2.0f, dot)), 0.0f);
            hi = j;
        }
        unsigned thr = __reduce_max_sync(full, __float_as_uint(hd));

        for (int j0 = 32; j0 < NN; j0 += 32) {
            int j = j0 + lane;
            float bxx = sx[j], byy = sy[j], bzz = sz[j];
            float rb  = __fadd_rn(__fadd_rn(__fmul_rn(bxx,bxx), __fmul_rn(byy,byy)), __fmul_rn(bzz,bzz));
            float dot = __fadd_rn(__fadd_rn(__fmul_rn(ax,bxx), __fmul_rn(ay,byy)), __fmul_rn(az,bzz));
            float d = fmaxf(__fsub_rn(__fadd_rn(ra, rb), __fmul_rn(2.0f, dot)), 0.0f);
            unsigned du = __float_as_uint(d);
            unsigned cm = __ballot_sync(full, du < thr);
            while (cm) {
                int src = __ffs(cm) - 1;
                cm &= cm - 1;
                unsigned cd = __shfl_sync(full, du, src);
                int ci = j0 + src;
                if (cd < thr) {
                    // evict the (thr, largest-idx) slot
                    unsigned hdu = __float_as_uint(hd);
                    int cand = (hdu == thr) ? hi : -1;
                    int evict = __reduce_max_sync(full, cand);
                    if (hdu == thr && hi == evict) { hd = __uint_as_float(cd); hi = ci; }
                    thr = __reduce_max_sync(full, __float_as_uint(hd));
                }
            }
        }
        g_gidx[((size_t)b*SS + s)*KK + lane] = hi;
    }
}

// =========================================================================
// Layer 1: gather(group) @ W1 [9->64], write x1, block-partial stats.
// thread = (row-lane rl 0..3, channel c 0..63); warp covers one row.
// =========================================================================
__global__ void __launch_bounds__(256) layer1_kernel(const float* __restrict__ xyz,
                                                     const float* __restrict__ feat,
                                                     const float* __restrict__ W1,
                                                     const float* __restrict__ cxyz)
{
    const int tid = threadIdx.x;
    const int c = tid & 63, rl = tid >> 6;
    float w[9];
    #pragma unroll
    for (int i = 0; i < 9; i++) w[i] = __ldg(&W1[i*64 + c]);

    float s = 0.f, q = 0.f;
    const int base = blockIdx.x * 256;
    #pragma unroll 4
    for (int m = 0; m < 64; m++) {
        int r = base + (m << 2) + rl;
        int k  = r & 31;      (void)k;
        int ss = (r >> 5) & (SS - 1);
        int bb = r >> 15;
        int gi = __ldg(&g_gidx[r]);
        float cx = __ldg(&cxyz[((size_t)bb*SS + ss)*3 + 0]);
        float cy = __ldg(&cxyz[((size_t)bb*SS + ss)*3 + 1]);
        float cz = __ldg(&cxyz[((size_t)bb*SS + ss)*3 + 2]);
        const float* p = xyz + ((size_t)bb*NN + gi)*3;
        const float* f = feat + ((size_t)bb*NN + gi)*DD;
        float g0 = __ldg(&p[0]) - cx;
        float g1 = __ldg(&p[1]) - cy;
        float g2 = __ldg(&p[2]) - cz;
        float acc = g0*w[0];
        acc = fmaf(g1, w[1], acc);
        acc = fmaf(g2, w[2], acc);
        #pragma unroll
        for (int i = 0; i < DD; i++) acc = fmaf(__ldg(&f[i]), w[3+i], acc);
        g_x1[(size_t)r*64 + c] = acc;
        s += acc; q = fmaf(acc, acc, q);
    }
    __shared__ float rs[4][64], rq[4][64];
    rs[rl][c] = s; rq[rl][c] = q;
    __syncthreads();
    if (rl == 0) {
        float ts = rs[0][c] + rs[1][c] + rs[2][c] + rs[3][c];
        float tq = rq[0][c] + rq[1][c] + rq[2][c] + rq[3][c];
        g_part1[blockIdx.x*128 + c]      = ts;
        g_part1[blockIdx.x*128 + 64 + c] = tq;
    }
}

// -------- BN finalize (deterministic fixed-order reductions) --------
__global__ void bn_reduce1(const float* __restrict__ g, const float* __restrict__ bv)
{
    int c = blockIdx.x;
    float s = 0.f, q = 0.f;
    for (int p = threadIdx.x; p < NB12; p += 256) {
        s += g_part1[p*128 + c];
        q += g_part1[p*128 + 64 + c];
    }
    __shared__ float ssm[256], qsm[256];
    ssm[threadIdx.x] = s; qsm[threadIdx.x] = q;
    __syncthreads();
    for (int o = 128; o > 0; o >>= 1) {
        if (threadIdx.x < o) { ssm[threadIdx.x] += ssm[threadIdx.x+o]; qsm[threadIdx.x] += qsm[threadIdx.x+o]; }
        __syncthreads();
    }
    if (threadIdx.x == 0) {
        float m = ssm[0] * (1.0f/524288.0f);
        float v = qsm[0] * (1.0f/524288.0f) - m*m;
        float sc = __ldg(&g[c]) * rsqrtf(v + 1e-5f);
        g_s1[c] = sc; g_bb1[c] = __ldg(&bv[c]) - m*sc;
    }
}
__global__ void bn_reduce2(const float* __restrict__ g, const float* __restrict__ bv)
{
    int c = blockIdx.x;
    float s = 0.f, q = 0.f;
    for (int p = threadIdx.x; p < NB12; p += 256) {
        s += g_part2[p*128 + c];
        q += g_part2[p*128 + 64 + c];
    }
    __shared__ float ssm[256], qsm[256];
    ssm[threadIdx.x] = s; qsm[threadIdx.x] = q;
    __syncthreads();
    for (int o = 128; o > 0; o >>= 1) {
        if (threadIdx.x < o) { ssm[threadIdx.x] += ssm[threadIdx.x+o]; qsm[threadIdx.x] += qsm[threadIdx.x+o]; }
        __syncthreads();
    }
    if (threadIdx.x == 0) {
        float m = ssm[0] * (1.0f/524288.0f);
        float v = qsm[0] * (1.0f/524288.0f) - m*m;
        float sc = __ldg(&g[c]) * rsqrtf(v + 1e-5f);
        g_s2[c] = sc; g_bb2[c] = __ldg(&bv[c]) - m*sc;
    }
}
__global__ void bn_reduce3(const float* __restrict__ g, const float* __restrict__ bv)
{
    int c = blockIdx.x;  // 128
    float s = 0.f, q = 0.f;
    for (int p = threadIdx.x; p < NB3; p += 256) {
        s += g_part3[(size_t)p*256 + c];
        q += g_part3[(size_t)p*256 + 128 + c];
    }
    __shared__ float ssm[256], qsm[256];
    ssm[threadIdx.x] = s; qsm[threadIdx.x] = q;
    __syncthreads();
    for (int o = 128; o > 0; o >>= 1) {
        if (threadIdx.x < o) { ssm[threadIdx.x] += ssm[threadIdx.x+o]; qsm[threadIdx.x] += qsm[threadIdx.x+o]; }
        __syncthreads();
    }
    if (threadIdx.x == 0) {
        float m = ssm[0] * (1.0f/524288.0f);
        float v = qsm[0] * (1.0f/524288.0f) - m*m;
        float sc = __ldg(&g[c]) * rsqrtf(v + 1e-5f);
        g_s3[c] = sc; g_bb3[c] = __ldg(&bv[c]) - m*sc;
    }
}

// =========================================================================
// Layer 2: x2 = relu(bn1(x1)) @ W2 [64->64], double-buffered smem h1.
// =========================================================================
__global__ void __launch_bounds__(256) layer2_kernel(const float* __restrict__ W2)
{
    const int tid = threadIdx.x;
    const int c = tid & 63, rl = tid >> 6;
    float w[64];
    #pragma unroll
    for (int i = 0; i < 64; i++) w[i] = __ldg(&W2[i*64 + c]);
    const float scl = g_s1[c], bia = g_bb1[c];   // load-phase channel == c

    __shared__ float sh[2][4][64];
    const int base = blockIdx.x * 256;
    {
        float v = g_x1[(size_t)(base + rl)*64 + c];
        sh[0][rl][c] = fmaxf(fmaf(v, scl, bia), 0.f);
    }
    float s = 0.f, q = 0.f;
    for (int p = 0; p < 64; p++) {
        __syncthreads();
        if (p + 1 < 64) {
            float v = g_x1[(size_t)(base + (p+1)*4 + rl)*64 + c];
            sh[(p+1)&1][rl][c] = fmaxf(fmaf(v, scl, bia), 0.f);
        }
        const float* hrow = &sh[p&1][rl][0];
        float acc = 0.f;
        #pragma unroll
        for (int i4 = 0; i4 < 16; i4++) {
            float4 hv = *(const float4*)(hrow + 4*i4);
            acc = fmaf(hv.x, w[4*i4+0], acc);
            acc = fmaf(hv.y, w[4*i4+1], acc);
            acc = fmaf(hv.z, w[4*i4+2], acc);
            acc = fmaf(hv.w, w[4*i4+3], acc);
        }
        int r = base + p*4 + rl;
        g_x2[(size_t)r*64 + c] = acc;
        s += acc; q = fmaf(acc, acc, q);
    }
    __syncthreads();
    __shared__ float rs[4][64], rq[4][64];
    rs[rl][c] = s; rq[rl][c] = q;
    __syncthreads();
    if (rl == 0) {
        float ts = rs[0][c] + rs[1][c] + rs[2][c] + rs[3][c];
        float tq = rq[0][c] + rq[1][c] + rq[2][c] + rq[3][c];
        g_part2[blockIdx.x*128 + c]      = ts;
        g_part2[blockIdx.x*128 + 64 + c] = tq;
    }
}

// =========================================================================
// Layer 3 fused: per (b,s): h2 = relu(bn2(x2)) -> x3 = h2 @ W3 [64->128]
// keep only per-channel max/min over k + stat partials (x3 never stored).
// =========================================================================
__global__ void __launch_bounds__(128) layer3_kernel(const float* __restrict__ W3)
{
    const int bs  = blockIdx.x;       // 0..16383
    const int c   = threadIdx.x;      // channel 0..127
    __shared__ float sh[32][64];      // h2, 8 KB

    #pragma unroll
    for (int m = 0; m < 16; m++) {
        int e = c + m*128;
        int k = e >> 6, i = e & 63;
        float v = g_x2[((size_t)bs*KK + k)*64 + i];
        sh[k][i] = fmaxf(fmaf(v, g_s2[i], g_bb2[i]), 0.f);
    }
    float w[64];
    #pragma unroll
    for (int i = 0; i < 64; i++) w[i] = __ldg(&W3[i*128 + c]);
    __syncthreads();

    float mx = -3.402823466e38f, mn = 3.402823466e38f, s = 0.f, q = 0.f;
    #pragma unroll 2
    for (int k = 0; k < KK; k++) {
        float acc = 0.f;
        #pragma unroll
        for (int i4 = 0; i4 < 16; i4++) {
            float4 hv = *(const float4*)(&sh[k][4*i4]);
            acc = fmaf(hv.x, w[4*i4+0], acc);
            acc = fmaf(hv.y, w[4*i4+1], acc);
            acc = fmaf(hv.z, w[4*i4+2], acc);
            acc = fmaf(hv.w, w[4*i4+3], acc);
        }
        mx = fmaxf(mx, acc); mn = fminf(mn, acc);
        s += acc; q = fmaf(acc, acc, q);
    }
    g_max3[(size_t)bs*128 + c] = mx;
    g_min3[(size_t)bs*128 + c] = mn;
    g_part3[(size_t)bs*256 + c]       = s;
    g_part3[(size_t)bs*256 + 128 + c] = q;
}

// final: out = relu(scale>=0 ? max*scale+bias : min*scale+bias)
__global__ void final_kernel(float* __restrict__ out_feat)
{
    int idx = blockIdx.x * 256 + threadIdx.x;   // < B*S*128
    int c = idx & 127;
    float sc = g_s3[c], bi = g_bb3[c];
    float v = (sc >= 0.f) ? g_max3[idx] : g_min3[idx];
    out_feat[idx] = fmaxf(fmaf(v, sc, bi), 0.f);
}

// =========================================================================
extern "C" void kernel_launch(void* const* d_in, const int* in_sizes, int n_in,
                              void* d_out, int out_size)
{
    const float* xyz  = (const float*)d_in[0];
    const float* feat = (const float*)d_in[1];
    const float* W1   = (const float*)d_in[2];
    const float* g1   = (const float*)d_in[3];
    const float* b1   = (const float*)d_in[4];
    const float* W2   = (const float*)d_in[5];
    const float* g2   = (const float*)d_in[6];
    const float* b2   = (const float*)d_in[7];
    const float* W3   = (const float*)d_in[8];
    const float* g3   = (const float*)d_in[9];
    const float* b3   = (const float*)d_in[10];

    float* out   = (float*)d_out;
    float* cxyz  = out;                      // [16,1024,3]
    float* ofeat = out + (size_t)BB*SS*3;    // [16,1024,128]

    fps_kernel   <<<BB, 512>>>(xyz, cxyz);
    knn_kernel   <<<BB*KNN_BPB, 256>>>(xyz, cxyz);
    layer1_kernel<<<NB12, 256>>>(xyz, feat, W1, cxyz);
    bn_reduce1   <<<64, 256>>>(g1, b1);
    layer2_kernel<<<NB12, 256>>>(W2);
    bn_reduce2   <<<64, 256>>>(g2, b2);
    layer3_kernel<<<NB3, 128>>>(W3);
    bn_reduce3   <<<128, 256>>>(g3, b3);
    final_kernel <<<(BB*SS*128)/256, 256>>>(ofeat);
}

// round 2
// speedup vs baseline: 1.0510x; 1.0510x over previous
#include <cuda_runtime.h>

// Problem constants
#define BB 16
#define NN 4096
#define DD 6
#define SS 1024          // NUM_CENTERS
#define KK 32
#define ROWS (BB*SS*KK)  // 524288
#define NB2  4096        // layer12 blocks (128 rows each)
#define NCTR (BB*SS)     // 16384 centers
#define KNN_BPB 32

// ---------------- device scratch ----------------
__device__ int   g_gidx[ROWS];                       // 2 MB
__device__ float g_x2[(size_t)ROWS*64];              // 128 MB
__device__ float g_gstat[128*64];                    // 128 blocks x 54(+pad)
__device__ float g_part2[NB2*128];
__device__ float g_part3[(size_t)NCTR*256];
__device__ float g_max3[(size_t)NCTR*128];
__device__ float g_min3[(size_t)NCTR*128];
__device__ float g_s1[64], g_b1o[64], g_s2[64], g_b2o[64], g_s3[128], g_b3o[128];

// packed f32x2 helpers
__device__ __forceinline__ void fma2acc(unsigned long long& acc,
                                        unsigned long long a, unsigned long long b) {
    asm("fma.rn.f32x2 %0, %1, %2, %0;" : "+l"(acc) : "l"(a), "l"(b));
}
__device__ __forceinline__ float f2lo(unsigned long long v){ return __uint_as_float((unsigned)v); }
__device__ __forceinline__ float f2hi(unsigned long long v){ return __uint_as_float((unsigned)(v>>32)); }

// =========================================================================
// FPS v2: one block/batch, 512 thr x 8 pts in regs, redux-based argmax,
// ONE barrier per iteration (double-buffered warp winners).
// =========================================================================
__global__ void __launch_bounds__(512) fps_kernel(const float* __restrict__ xyz,
                                                  float* __restrict__ out_cxyz)
{
    extern __shared__ float fsm[];
    float* sxx = fsm; float* syy = fsm + NN; float* szz = fsm + 2*NN;
    __shared__ unsigned long long sw[2][16];

    const int b   = blockIdx.x;
    const int tid = threadIdx.x;
    const float* bx = xyz + (size_t)b * NN * 3;

    for (int idx = tid; idx < NN; idx += 512) {
        sxx[idx] = bx[idx*3+0]; syy[idx] = bx[idx*3+1]; szz[idx] = bx[idx*3+2];
    }
    __syncthreads();

    float px[8], py[8], pz[8], dmin[8];
    #pragma unroll
    for (int i = 0; i < 8; i++) {
        int j = tid*8 + i;
        px[i] = sxx[j]; py[i] = syy[j]; pz[i] = szz[j];
    }
    float c0x = sxx[0], c0y = syy[0], c0z = szz[0];
    #pragma unroll
    for (int i = 0; i < 8; i++) {
        float dx = __fsub_rn(px[i], c0x);
        float dy = __fsub_rn(py[i], c0y);
        float dz = __fsub_rn(pz[i], c0z);
        dmin[i] = __fadd_rn(__fadd_rn(__fmul_rn(dx,dx), __fmul_rn(dy,dy)), __fmul_rn(dz,dz));
    }
    if (tid == 0) {
        out_cxyz[(size_t)b*SS*3+0] = c0x;
        out_cxyz[(size_t)b*SS*3+1] = c0y;
        out_cxyz[(size_t)b*SS*3+2] = c0z;
    }

    const int lane = tid & 31, warp = tid >> 5;
    const unsigned full = 0xFFFFFFFFu;

    for (int t = 1; t < SS; t++) {
        // thread-local argmax (first occurrence on tie: strict >)
        float db = dmin[0]; int bi_ = tid*8;
        #pragma unroll
        for (int i = 1; i < 8; i++) if (dmin[i] > db) { db = dmin[i]; bi_ = tid*8 + i; }
        unsigned dmax = __reduce_max_sync(full, __float_as_uint(db));   // d>=0: monotone bits
        unsigned cand = (__float_as_uint(db) == dmax) ? (unsigned)bi_ : 0xFFFFFFFFu;
        unsigned imin = __reduce_min_sync(full, cand);
        if (lane == 0)
            sw[t&1][warp] = ((unsigned long long)dmax << 32) | (unsigned)(0xFFFFFFFFu - imin);
        __syncthreads();

        unsigned long long v[16];
        #pragma unroll
        for (int w = 0; w < 16; w++) v[w] = sw[t&1][w];
        #pragma unroll
        for (int st = 8; st > 0; st >>= 1)
            #pragma unroll
            for (int w = 0; w < 8; w++) if (w < st) v[w] = (v[w] > v[w+st]) ? v[w] : v[w+st];
        int idx = (int)(0xFFFFFFFFu - (unsigned)v[0]);

        float cx = sxx[idx], cy = syy[idx], cz = szz[idx];
        if (tid == 0) {
            out_cxyz[((size_t)b*SS + t)*3+0] = cx;
            out_cxyz[((size_t)b*SS + t)*3+1] = cy;
            out_cxyz[((size_t)b*SS + t)*3+2] = cz;
        }
        #pragma unroll
        for (int i = 0; i < 8; i++) {
            float dx = __fsub_rn(px[i], cx);
            float dy = __fsub_rn(py[i], cy);
            float dz = __fsub_rn(pz[i], cz);
            float d = __fadd_rn(__fadd_rn(__fmul_rn(dx,dx), __fmul_rn(dy,dy)), __fmul_rn(dz,dz));
            dmin[i] = fminf(dmin[i], d);
        }
    }
}

// =========================================================================
// kNN: unchanged from R1 (warp/center streaming top-32).
// =========================================================================
__global__ void __launch_bounds__(256) knn_kernel(const float* __restrict__ xyz,
                                                  const float* __restrict__ cxyz)
{
    __shared__ float sx[NN], sy[NN], sz[NN];
    const int b     = blockIdx.x >> 5;
    const int blkin = blockIdx.x & 31;
    const int tid   = threadIdx.x;
    const float* bx = xyz + (size_t)b * NN * 3;

    for (int j = tid; j < NN; j += 256) {
        sx[j] = bx[j*3+0]; sy[j] = bx[j*3+1]; sz[j] = bx[j*3+2];
    }
    __syncthreads();

    const int warp = tid >> 5, lane = tid & 31;
    const unsigned full = 0xFFFFFFFFu;

    for (int m = 0; m < 4; m++) {
        int s = (blkin * 8 + warp) * 4 + m;
        float ax = cxyz[((size_t)b*SS + s)*3+0];
        float ay = cxyz[((size_t)b*SS + s)*3+1];
        float az = cxyz[((size_t)b*SS + s)*3+2];
        float ra = __fadd_rn(__fadd_rn(__fmul_rn(ax,ax), __fmul_rn(ay,ay)), __fmul_rn(az,az));

        float hd; int hi;
        {
            int j = lane;
            float bxx = sx[j], byy = sy[j], bzz = sz[j];
            float rb  = __fadd_rn(__fadd_rn(__fmul_rn(bxx,bxx), __fmul_rn(byy,byy)), __fmul_rn(bzz,bzz));
            float dot = __fadd_rn(__fadd_rn(__fmul_rn(ax,bxx), __fmul_rn(ay,byy)), __fmul_rn(az,bzz));
            hd = fmaxf(__fsub_rn(__fadd_rn(ra, rb), __fmul_rn(2.0f, dot)), 0.0f);
            hi = j;
        }
        unsigned thr = __reduce_max_sync(full, __float_as_uint(hd));

        for (int j0 = 32; j0 < NN; j0 += 32) {
            int j = j0 + lane;
            float bxx = sx[j], byy = sy[j], bzz = sz[j];
            float rb  = __fadd_rn(__fadd_rn(__fmul_rn(bxx,bxx), __fmul_rn(byy,byy)), __fmul_rn(bzz,bzz));
            float dot = __fadd_rn(__fadd_rn(__fmul_rn(ax,bxx), __fmul_rn(ay,byy)), __fmul_rn(az,bzz));
            float d = fmaxf(__fsub_rn(__fadd_rn(ra, rb), __fmul_rn(2.0f, dot)), 0.0f);
            unsigned du = __float_as_uint(d);
            unsigned cm = __ballot_sync(full, du < thr);
            while (cm) {
                int src = __ffs(cm) - 1;
                cm &= cm - 1;
                unsigned cd = __shfl_sync(full, du, src);
                int ci = j0 + src;
                if (cd < thr) {
                    unsigned hdu = __float_as_uint(hd);
                    int candi = (hdu == thr) ? hi : -1;
                    int evict = __reduce_max_sync(full, candi);
                    if (hdu == thr && hi == evict) { hd = __uint_as_float(cd); hi = ci; }
                    thr = __reduce_max_sync(full, __float_as_uint(hd));
                }
            }
        }
        g_gidx[((size_t)b*SS + s)*KK + lane] = hi;
    }
}

// =========================================================================
// G stats: mean(9) + second moments (45) of gathered group input.
// 128 blocks x 256 threads x 16 rows.
// =========================================================================
__global__ void __launch_bounds__(256) gstats_kernel(const float* __restrict__ xyz,
                                                     const float* __restrict__ feat,
                                                     const float* __restrict__ cxyz)
{
    const int tid = threadIdx.x;
    const int t0  = blockIdx.x * 4096 + tid;
    float s[9]; float m2[45];
    #pragma unroll
    for (int i = 0; i < 9; i++) s[i] = 0.f;
    #pragma unroll
    for (int i = 0; i < 45; i++) m2[i] = 0.f;

    for (int m = 0; m < 16; m++) {
        int r = t0 + m*256;
        int bb = r >> 15, ssi = (r >> 5) & (SS-1);
        int gi = __ldg(&g_gidx[r]);
        const float* c = cxyz + ((size_t)bb*SS + ssi)*3;
        const float* p = xyz  + ((size_t)bb*NN + gi)*3;
        const float* f = feat + ((size_t)bb*NN + gi)*DD;
        float g[9];
        g[0] = __ldg(&p[0]) - __ldg(&c[0]);
        g[1] = __ldg(&p[1]) - __ldg(&c[1]);
        g[2] = __ldg(&p[2]) - __ldg(&c[2]);
        #pragma unroll
        for (int i = 0; i < DD; i++) g[3+i] = __ldg(&f[i]);
        #pragma unroll
        for (int i = 0; i < 9; i++) s[i] += g[i];
        int k = 0;
        #pragma unroll
        for (int i = 0; i < 9; i++)
            #pragma unroll
            for (int j = i; j < 9; j++) { m2[k] = fmaf(g[i], g[j], m2[k]); k++; }
    }
    const unsigned full = 0xFFFFFFFFu;
    #pragma unroll
    for (int q = 0; q < 9; q++)
        for (int o = 16; o > 0; o >>= 1) s[q] += __shfl_xor_sync(full, s[q], o);
    #pragma unroll
    for (int q = 0; q < 45; q++)
        for (int o = 16; o > 0; o >>= 1) m2[q] += __shfl_xor_sync(full, m2[q], o);

    __shared__ float sred[8][56];
    const int lane = tid & 31, warp = tid >> 5;
    if (lane == 0) {
        #pragma unroll
        for (int q = 0; q < 9; q++)  sred[warp][q]   = s[q];
        #pragma unroll
        for (int q = 0; q < 45; q++) sred[warp][9+q] = m2[q];
    }
    __syncthreads();
    if (tid < 54) {
        float a = 0.f;
        #pragma unroll
        for (int w = 0; w < 8; w++) a += sred[w][tid];
        g_gstat[blockIdx.x*64 + tid] = a;
    }
}

// BN1 solve from moments (exact: x1 linear in g). fp64 for the tiny solve.
__global__ void bn1_solve(const float* __restrict__ W1,
                          const float* __restrict__ g1v, const float* __restrict__ b1v)
{
    __shared__ double st[54];
    const int t = threadIdx.x;
    if (t < 54) {
        double a = 0.0;
        for (int p = 0; p < 128; p++) a += (double)g_gstat[p*64 + t];
        st[t] = a;
    }
    __syncthreads();
    const double Ri = 1.0 / 524288.0;
    double w[9];
    #pragma unroll
    for (int i = 0; i < 9; i++) w[i] = (double)__ldg(&W1[i*64 + t]);
    double m1 = 0.0;
    #pragma unroll
    for (int i = 0; i < 9; i++) m1 += st[i]*Ri*w[i];
    double e2 = 0.0; int k = 0;
    #pragma unroll
    for (int i = 0; i < 9; i++)
        #pragma unroll
        for (int j = i; j < 9; j++) {
            double term = st[9+k]*Ri*w[i]*w[j];
            e2 += (i == j) ? term : 2.0*term;
            k++;
        }
    double var = e2 - m1*m1;
    double sc = (double)__ldg(&g1v[t]) / sqrt(var + 1e-5);
    g_s1[t]  = (float)sc;
    g_b1o[t] = (float)((double)__ldg(&b1v[t]) - m1*sc);
}

// =========================================================================
// Fused layer1+2: gather -> x1(9->64) -> bn1/relu -> x2 = h1 @ W2 (FFMA2)
// 4096 blocks x 128 rows. Dyn smem: sg[128][10] | shd[128][132] | w2s[64][64]
// | rs[32][64] | rq[32][64]
// =========================================================================
#define L12_SMEM (26368*4)
__global__ void __launch_bounds__(256) layer12_kernel(const float* __restrict__ xyz,
                                                      const float* __restrict__ feat,
                                                      const float* __restrict__ cxyz,
                                                      const float* __restrict__ W1,
                                                      const float* __restrict__ W2)
{
    extern __shared__ float dyn[];
    float* sg  = dyn;            // 1280
    float* shd = dyn + 1280;     // 16896
    float* w2s = shd + 16896;    // 4096
    float* rs  = w2s + 4096;     // 2048
    float* rq  = rs  + 2048;     // 2048

    const int tid = threadIdx.x;
    const int rowbase = blockIdx.x * 128;

    for (int i = tid; i < 4096; i += 256) w2s[i] = __ldg(&W2[i]);

    if (tid < 128) {
        int r = rowbase + tid;
        int bb = r >> 15, ssi = (r >> 5) & (SS-1);
        int gi = __ldg(&g_gidx[r]);
        const float* c = cxyz + ((size_t)bb*SS + ssi)*3;
        const float* p = xyz  + ((size_t)bb*NN + gi)*3;
        const float* f = feat + ((size_t)bb*NN + gi)*DD;
        float* gg = sg + tid*10;
        gg[0] = __ldg(&p[0]) - __ldg(&c[0]);
        gg[1] = __ldg(&p[1]) - __ldg(&c[1]);
        gg[2] = __ldg(&p[2]) - __ldg(&c[2]);
        #pragma unroll
        for (int i = 0; i < DD; i++) gg[3+i] = __ldg(&f[i]);
    }
    __syncthreads();

    // x1 + bn1 + relu -> duplicated h1
    {
        const int c2 = tid & 31, r0 = tid >> 5;
        float wa[9], wb[9];
        #pragma unroll
        for (int i = 0; i < 9; i++) {
            wa[i] = __ldg(&W1[i*64 + 2*c2]);
            wb[i] = __ldg(&W1[i*64 + 2*c2 + 1]);
        }
        const float sa = g_s1[2*c2], sb = g_s1[2*c2+1];
        const float ba = g_b1o[2*c2], bbv = g_b1o[2*c2+1];
        #pragma unroll 4
        for (int m = 0; m < 16; m++) {
            int row = r0 + 8*m;
            const float* gg = sg + row*10;
            float xa = gg[0]*wa[0], xb = gg[0]*wb[0];
            #pragma unroll
            for (int i = 1; i < 9; i++) { float gv = gg[i]; xa = fmaf(gv, wa[i], xa); xb = fmaf(gv, wb[i], xb); }
            float ha = fmaxf(fmaf(xa, sa, ba), 0.f);
            float hb = fmaxf(fmaf(xb, sb, bbv), 0.f);
            *(float4*)&shd[row*132 + 4*c2] = make_float4(ha, ha, hb, hb);
        }
    }
    __syncthreads();

    // GEMM: thread tile 4 rows x 4 channel-pairs (8 channels), FFMA2
    const int ct = tid & 7, rt = tid >> 3;
    unsigned long long acc[4][4];
    #pragma unroll
    for (int r = 0; r < 4; r++)
        #pragma unroll
        for (int p = 0; p < 4; p++) acc[r][p] = 0ULL;

    #pragma unroll 4
    for (int i = 0; i < 64; i++) {
        ulonglong2 w01 = *(const ulonglong2*)&w2s[i*64 + 8*ct];
        ulonglong2 w23 = *(const ulonglong2*)&w2s[i*64 + 8*ct + 4];
        unsigned long long h0 = *(const unsigned long long*)&shd[(4*rt+0)*132 + 2*i];
        unsigned long long h1 = *(const unsigned long long*)&shd[(4*rt+1)*132 + 2*i];
        unsigned long long h2 = *(const unsigned long long*)&shd[(4*rt+2)*132 + 2*i];
        unsigned long long h3 = *(const unsigned long long*)&shd[(4*rt+3)*132 + 2*i];
        fma2acc(acc[0][0], h0, w01.x); fma2acc(acc[0][1], h0, w01.y);
        fma2acc(acc[0][2], h0, w23.x); fma2acc(acc[0][3], h0, w23.y);
        fma2acc(acc[1][0], h1, w01.x); fma2acc(acc[1][1], h1, w01.y);
        fma2acc(acc[1][2], h1, w23.x); fma2acc(acc[1][3], h1, w23.y);
        fma2acc(acc[2][0], h2, w01.x); fma2acc(acc[2][1], h2, w01.y);
        fma2acc(acc[2][2], h2, w23.x); fma2acc(acc[2][3], h2, w23.y);
        fma2acc(acc[3][0], h3, w01.x); fma2acc(acc[3][1], h3, w01.y);
        fma2acc(acc[3][2], h3, w23.x); fma2acc(acc[3][3], h3, w23.y);
    }

    float cs[8], cq[8];
    #pragma unroll
    for (int j = 0; j < 8; j++) { cs[j] = 0.f; cq[j] = 0.f; }
    #pragma unroll
    for (int r = 0; r < 4; r++) {
        int grow = rowbase + 4*rt + r;
        float o[8];
        #pragma unroll
        for (int p = 0; p < 4; p++) { o[2*p] = f2lo(acc[r][p]); o[2*p+1] = f2hi(acc[r][p]); }
        *(float4*)&g_x2[(size_t)grow*64 + 8*ct]     = make_float4(o[0], o[1], o[2], o[3]);
        *(float4*)&g_x2[(size_t)grow*64 + 8*ct + 4] = make_float4(o[4], o[5], o[6], o[7]);
        #pragma unroll
        for (int j = 0; j < 8; j++) { cs[j] += o[j]; cq[j] = fmaf(o[j], o[j], cq[j]); }
    }
    #pragma unroll
    for (int j = 0; j < 8; j++) { rs[rt*64 + 8*ct + j] = cs[j]; rq[rt*64 + 8*ct + j] = cq[j]; }
    __syncthreads();
    if (tid < 64) {
        float a = 0.f, qq = 0.f;
        for (int r2 = 0; r2 < 32; r2++) { a += rs[r2*64 + tid]; qq += rq[r2*64 + tid]; }
        g_part2[blockIdx.x*128 + tid]      = a;
        g_part2[blockIdx.x*128 + 64 + tid] = qq;
    }
}

__global__ void bn_reduce2(const float* __restrict__ g, const float* __restrict__ bv)
{
    int c = blockIdx.x;
    float s = 0.f, q = 0.f;
    for (int p = threadIdx.x; p < NB2; p += 256) {
        s += g_part2[p*128 + c];
        q += g_part2[p*128 + 64 + c];
    }
    __shared__ float ssm[256], qsm[256];
    ssm[threadIdx.x] = s; qsm[threadIdx.x] = q;
    __syncthreads();
    for (int o = 128; o > 0; o >>= 1) {
        if (threadIdx.x < o) { ssm[threadIdx.x] += ssm[threadIdx.x+o]; qsm[threadIdx.x] += qsm[threadIdx.x+o]; }
        __syncthreads();
    }
    if (threadIdx.x == 0) {
        float m = ssm[0] * (1.0f/524288.0f);
        float v = qsm[0] * (1.0f/524288.0f) - m*m;
        float sc = __ldg(&g[c]) * rsqrtf(v + 1e-5f);
        g_s2[c] = sc; g_b2o[c] = __ldg(&bv[c]) - m*sc;
    }
}

// =========================================================================
// Layer 3 fused (FFMA2): 2048 blocks x 8 centers. Per center: bn2/relu ->
// h2 dup -> x3 = h2 @ W3 with per-channel max/min + stat partials.
// Dyn smem: w3s[64][128] | shd[32][132] | rmx/rmn/rsm/rsq[8][128]
// =========================================================================
#define L3_SMEM (16512*4)
__global__ void __launch_bounds__(256) layer3_kernel(const float* __restrict__ W3)
{
    extern __shared__ float dyn[];
    float* w3s = dyn;            // 8192
    float* shd = dyn + 8192;     // 4224
    float* rmx = shd + 4224;     // 1024
    float* rmn = rmx + 1024;     // 1024
    float* rsm = rmn + 1024;     // 1024
    float* rsq = rsm + 1024;     // 1024

    const int tid = threadIdx.x;
    for (int i = tid; i < 8192; i += 256) w3s[i] = __ldg(&W3[i]);

    const int c2 = tid & 31, kq = tid >> 5;
    const float s2a = g_s2[2*c2], s2b = g_s2[2*c2+1];
    const float b2a = g_b2o[2*c2], b2b = g_b2o[2*c2+1];
    const int ct = tid & 31, kt = tid >> 5;

    for (int cc = 0; cc < 8; cc++) {
        const int bs = blockIdx.x*8 + cc;
        __syncthreads();   // guards shd/red reuse (and w3s staging on cc==0)

        #pragma unroll
        for (int m = 0; m < 4; m++) {
            int kk = kq + 8*m;
            float2 v = *(const float2*)&g_x2[((size_t)bs*KK + kk)*64 + 2*c2];
            float ha = fmaxf(fmaf(v.x, s2a, b2a), 0.f);
            float hb = fmaxf(fmaf(v.y, s2b, b2b), 0.f);
            *(float4*)&shd[kk*132 + 4*c2] = make_float4(ha, ha, hb, hb);
        }
        __syncthreads();

        unsigned long long acc[4][2];
        #pragma unroll
        for (int r = 0; r < 4; r++) { acc[r][0] = 0ULL; acc[r][1] = 0ULL; }

        #pragma unroll 4
        for (int i = 0; i < 64; i++) {
            ulonglong2 wv = *(const ulonglong2*)&w3s[i*128 + 4*ct];
            unsigned long long h0 = *(const unsigned long long*)&shd[(4*kt+0)*132 + 2*i];
            unsigned long long h1 = *(const unsigned long long*)&shd[(4*kt+1)*132 + 2*i];
            unsigned long long h2 = *(const unsigned long long*)&shd[(4*kt+2)*132 + 2*i];
            unsigned long long h3 = *(const unsigned long long*)&shd[(4*kt+3)*132 + 2*i];
            fma2acc(acc[0][0], h0, wv.x); fma2acc(acc[0][1], h0, wv.y);
            fma2acc(acc[1][0], h1, wv.x); fma2acc(acc[1][1], h1, wv.y);
            fma2acc(acc[2][0], h2, wv.x); fma2acc(acc[2][1], h2, wv.y);
            fma2acc(acc[3][0], h3, wv.x); fma2acc(acc[3][1], h3, wv.y);
        }

        float mx[4], mn[4], sm[4], sq[4];
        #pragma unroll
        for (int j = 0; j < 4; j++) { mx[j] = -3.402823466e38f; mn[j] = 3.402823466e38f; sm[j] = 0.f; sq[j] = 0.f; }
        #pragma unroll
        for (int r = 0; r < 4; r++) {
            float o[4];
            o[0] = f2lo(acc[r][0]); o[1] = f2hi(acc[r][0]);
            o[2] = f2lo(acc[r][1]); o[3] = f2hi(acc[r][1]);
            #pragma unroll
            for (int j = 0; j < 4; j++) {
                mx[j] = fmaxf(mx[j], o[j]); mn[j] = fminf(mn[j], o[j]);
                sm[j] += o[j]; sq[j] = fmaf(o[j], o[j], sq[j]);
            }
        }
        #pragma unroll
        for (int j = 0; j < 4; j++) {
            rmx[kt*128 + 4*ct + j] = mx[j];
            rmn[kt*128 + 4*ct + j] = mn[j];
            rsm[kt*128 + 4*ct + j] = sm[j];
            rsq[kt*128 + 4*ct + j] = sq[j];
        }
        __syncthreads();
        if (tid < 128) {
            float a = rmx[tid], bm = rmn[tid], s_ = rsm[tid], q_ = rsq[tid];
            #pragma unroll
            for (int k2 = 1; k2 < 8; k2++) {
                a  = fmaxf(a,  rmx[k2*128 + tid]);
                bm = fminf(bm, rmn[k2*128 + tid]);
                s_ += rsm[k2*128 + tid];
                q_ += rsq[k2*128 + tid];
            }
            g_max3[(size_t)bs*128 + tid] = a;
            g_min3[(size_t)bs*128 + tid] = bm;
            g_part3[(size_t)bs*256 + tid]       = s_;
            g_part3[(size_t)bs*256 + 128 + tid] = q_;
        }
    }
}

__global__ void bn_reduce3(const float* __restrict__ g, const float* __restrict__ bv)
{
    int c = blockIdx.x;  // 128
    float s = 0.f, q = 0.f;
    for (int p = threadIdx.x; p < NCTR; p += 256) {
        s += g_part3[(size_t)p*256 + c];
        q += g_part3[(size_t)p*256 + 128 + c];
    }
    __shared__ float ssm[256], qsm[256];
    ssm[threadIdx.x] = s; qsm[threadIdx.x] = q;
    __syncthreads();
    for (int o = 128; o > 0; o >>= 1) {
        if (threadIdx.x < o) { ssm[threadIdx.x] += ssm[threadIdx.x+o]; qsm[threadIdx.x] += qsm[threadIdx.x+o]; }
        __syncthreads();
    }
    if (threadIdx.x == 0) {
        float m = ssm[0] * (1.0f/524288.0f);
        float v = qsm[0] * (1.0f/524288.0f) - m*m;
        float sc = __ldg(&g[c]) * rsqrtf(v + 1e-5f);
        g_s3[c] = sc; g_b3o[c] = __ldg(&bv[c]) - m*sc;
    }
}

// max_k relu(s*x+b) = relu(s*(s>=0? max:min) + b)  (monotone relu + uniform slope)
__global__ void final_kernel(float* __restrict__ out_feat)
{
    int idx = blockIdx.x * 256 + threadIdx.x;
    int c = idx & 127;
    float sc = g_s3[c], bi = g_b3o[c];
    float v = (sc >= 0.f) ? g_max3[idx] : g_min3[idx];
    out_feat[idx] = fmaxf(fmaf(v, sc, bi), 0.f);
}

// =========================================================================
extern "C" void kernel_launch(void* const* d_in, const int* in_sizes, int n_in,
                              void* d_out, int out_size)
{
    const float* xyz  = (const float*)d_in[0];
    const float* feat = (const float*)d_in[1];
    const float* W1   = (const float*)d_in[2];
    const float* g1   = (const float*)d_in[3];
    const float* b1   = (const float*)d_in[4];
    const float* W2   = (const float*)d_in[5];
    const float* g2   = (const float*)d_in[6];
    const float* b2   = (const float*)d_in[7];
    const float* W3   = (const float*)d_in[8];
    const float* g3   = (const float*)d_in[9];
    const float* b3   = (const float*)d_in[10];

    float* out   = (float*)d_out;
    float* cxyz  = out;                      // [16,1024,3]
    float* ofeat = out + (size_t)BB*SS*3;    // [16,1024,128]

    cudaFuncSetAttribute(fps_kernel,     cudaFuncAttributeMaxDynamicSharedMemorySize, NN*3*4);
    cudaFuncSetAttribute(layer12_kernel, cudaFuncAttributeMaxDynamicSharedMemorySize, L12_SMEM);
    cudaFuncSetAttribute(layer3_kernel,  cudaFuncAttributeMaxDynamicSharedMemorySize, L3_SMEM);

    fps_kernel    <<<BB, 512, NN*3*4>>>(xyz, cxyz);
    knn_kernel    <<<BB*KNN_BPB, 256>>>(xyz, cxyz);
    gstats_kernel <<<128, 256>>>(xyz, feat, cxyz);
    bn1_solve     <<<1, 64>>>(W1, g1, b1);
    layer12_kernel<<<NB2, 256, L12_SMEM>>>(xyz, feat, cxyz, W1, W2);
    bn_reduce2    <<<64, 256>>>(g2, b2);
    layer3_kernel <<<NCTR/8, 256, L3_SMEM>>>(W3);
    bn_reduce3    <<<128, 256>>>(g3, b3);
    final_kernel  <<<(BB*SS*128)/256, 256>>>(ofeat);
}

// round 3
// speedup vs baseline: 1.1244x; 1.0699x over previous
#include <cuda_runtime.h>

// Problem constants
#define BB 16
#define NN 4096
#define DD 6
#define SS 1024          // NUM_CENTERS
#define KK 32
#define ROWS (BB*SS*KK)  // 524288
#define NB2  4096        // layer12 blocks (128 rows each)
#define NCTR (BB*SS)     // 16384 centers
#define KNN_BPB 32
#define GSB 512          // gstats blocks

// ---------------- device scratch ----------------
__device__ int   g_gidx[ROWS];                       // 2 MB
__device__ float g_x2[(size_t)ROWS*64];              // 128 MB
__device__ float g_gstat[GSB*64];
__device__ float g_part2[NB2*128];
__device__ float g_part3[(size_t)NCTR*256];
__device__ float g_max3[(size_t)NCTR*128];
__device__ float g_min3[(size_t)NCTR*128];
__device__ float g_s1[64], g_b1o[64], g_s2[64], g_b2o[64], g_s3[128], g_b3o[128];

// packed f32x2 helpers
__device__ __forceinline__ void fma2acc(unsigned long long& acc,
                                        unsigned long long a, unsigned long long b) {
    asm("fma.rn.f32x2 %0, %1, %2, %0;" : "+l"(acc) : "l"(a), "l"(b));
}
__device__ __forceinline__ float f2lo(unsigned long long v){ return __uint_as_float((unsigned)v); }
__device__ __forceinline__ float f2hi(unsigned long long v){ return __uint_as_float((unsigned)(v>>32)); }

// =========================================================================
// FPS v3: one block/batch, 512 thr x 8 pts in regs. Local argmax fused into
// the dmin-update loop; redux-based warp argmax; ONE barrier/iter
// (double-buffered winners); winners loaded as LDS.128.
// =========================================================================
__global__ void __launch_bounds__(512) fps_kernel(const float* __restrict__ xyz,
                                                  float* __restrict__ out_cxyz)
{
    extern __shared__ float fsm[];
    float* sxx = fsm; float* syy = fsm + NN; float* szz = fsm + 2*NN;
    __shared__ unsigned long long sw[2][16];

    const int b   = blockIdx.x;
    const int tid = threadIdx.x;
    const float* bx = xyz + (size_t)b * NN * 3;

    for (int idx = tid; idx < NN; idx += 512) {
        sxx[idx] = bx[idx*3+0]; syy[idx] = bx[idx*3+1]; szz[idx] = bx[idx*3+2];
    }
    __syncthreads();

    float px[8], py[8], pz[8], dmin[8];
    #pragma unroll
    for (int i = 0; i < 8; i++) {
        int j = tid*8 + i;
        px[i] = sxx[j]; py[i] = syy[j]; pz[i] = szz[j];
    }
    float c0x = sxx[0], c0y = syy[0], c0z = szz[0];
    float db = -1.0f; int bi_ = tid*8;
    #pragma unroll
    for (int i = 0; i < 8; i++) {
        float dx = __fsub_rn(px[i], c0x);
        float dy = __fsub_rn(py[i], c0y);
        float dz = __fsub_rn(pz[i], c0z);
        dmin[i] = __fadd_rn(__fadd_rn(__fmul_rn(dx,dx), __fmul_rn(dy,dy)), __fmul_rn(dz,dz));
        if (dmin[i] > db) { db = dmin[i]; bi_ = tid*8 + i; }   // first-occurrence
    }
    if (tid == 0) {
        out_cxyz[(size_t)b*SS*3+0] = c0x;
        out_cxyz[(size_t)b*SS*3+1] = c0y;
        out_cxyz[(size_t)b*SS*3+2] = c0z;
    }

    const int lane = tid & 31, warp = tid >> 5;
    const unsigned full = 0xFFFFFFFFu;

    for (int t = 1; t < SS; t++) {
        unsigned dmax = __reduce_max_sync(full, __float_as_uint(db));
        unsigned cand = (__float_as_uint(db) == dmax) ? (unsigned)bi_ : 0xFFFFFFFFu;
        unsigned imin = __reduce_min_sync(full, cand);
        if (lane == 0)
            sw[t&1][warp] = ((unsigned long long)dmax << 32) | (unsigned)(0xFFFFFFFFu - imin);
        __syncthreads();

        const ulonglong2* pw = (const ulonglong2*)sw[t&1];
        unsigned long long v[8];
        #pragma unroll
        for (int w = 0; w < 8; w++) {
            ulonglong2 q = pw[w];
            v[w] = (q.x > q.y) ? q.x : q.y;
        }
        #pragma unroll
        for (int st = 4; st > 0; st >>= 1)
            #pragma unroll
            for (int w = 0; w < 4; w++) if (w < st) v[w] = (v[w] > v[w+st]) ? v[w] : v[w+st];
        int idx = (int)(0xFFFFFFFFu - (unsigned)v[0]);

        float cx = sxx[idx], cy = syy[idx], cz = szz[idx];
        if (tid == 0) {
            out_cxyz[((size_t)b*SS + t)*3+0] = cx;
            out_cxyz[((size_t)b*SS + t)*3+1] = cy;
            out_cxyz[((size_t)b*SS + t)*3+2] = cz;
        }
        db = -1.0f; bi_ = tid*8;
        #pragma unroll
        for (int i = 0; i < 8; i++) {
            float dx = __fsub_rn(px[i], cx);
            float dy = __fsub_rn(py[i], cy);
            float dz = __fsub_rn(pz[i], cz);
            float d = __fadd_rn(__fadd_rn(__fmul_rn(dx,dx), __fmul_rn(dy,dy)), __fmul_rn(dz,dz));
            dmin[i] = fminf(dmin[i], d);
            if (dmin[i] > db) { db = dmin[i]; bi_ = tid*8 + i; }
        }
    }
}

// =========================================================================
// kNN: warp/center streaming top-32 (unchanged; bit-identical policy).
// =========================================================================
__global__ void __launch_bounds__(256) knn_kernel(const float* __restrict__ xyz,
                                                  const float* __restrict__ cxyz)
{
    __shared__ float sx[NN], sy[NN], sz[NN];
    const int b     = blockIdx.x >> 5;
    const int blkin = blockIdx.x & 31;
    const int tid   = threadIdx.x;
    const float* bx = xyz + (size_t)b * NN * 3;

    for (int j = tid; j < NN; j += 256) {
        sx[j] = bx[j*3+0]; sy[j] = bx[j*3+1]; sz[j] = bx[j*3+2];
    }
    __syncthreads();

    const int warp = tid >> 5, lane = tid & 31;
    const unsigned full = 0xFFFFFFFFu;

    for (int m = 0; m < 4; m++) {
        int s = (blkin * 8 + warp) * 4 + m;
        float ax = cxyz[((size_t)b*SS + s)*3+0];
        float ay = cxyz[((size_t)b*SS + s)*3+1];
        float az = cxyz[((size_t)b*SS + s)*3+2];
        float ra = __fadd_rn(__fadd_rn(__fmul_rn(ax,ax), __fmul_rn(ay,ay)), __fmul_rn(az,az));

        float hd; int hi;
        {
            int j = lane;
            float bxx = sx[j], byy = sy[j], bzz = sz[j];
            float rb  = __fadd_rn(__fadd_rn(__fmul_rn(bxx,bxx), __fmul_rn(byy,byy)), __fmul_rn(bzz,bzz));
            float dot = __fadd_rn(__fadd_rn(__fmul_rn(ax,bxx), __fmul_rn(ay,byy)), __fmul_rn(az,bzz));
            hd = fmaxf(__fsub_rn(__fadd_rn(ra, rb), __fmul_rn(2.0f, dot)), 0.0f);
            hi = j;
        }
        unsigned thr = __reduce_max_sync(full, __float_as_uint(hd));

        for (int j0 = 32; j0 < NN; j0 += 32) {
            int j = j0 + lane;
            float bxx = sx[j], byy = sy[j], bzz = sz[j];
            float rb  = __fadd_rn(__fadd_rn(__fmul_rn(bxx,bxx), __fmul_rn(byy,byy)), __fmul_rn(bzz,bzz));
            float dot = __fadd_rn(__fadd_rn(__fmul_rn(ax,bxx), __fmul_rn(ay,byy)), __fmul_rn(az,bzz));
            float d = fmaxf(__fsub_rn(__fadd_rn(ra, rb), __fmul_rn(2.0f, dot)), 0.0f);
            unsigned du = __float_as_uint(d);
            unsigned cm = __ballot_sync(full, du < thr);
            while (cm) {
                int src = __ffs(cm) - 1;
                cm &= cm - 1;
                unsigned cd = __shfl_sync(full, du, src);
                int ci = j0 + src;
                if (cd < thr) {
                    unsigned hdu = __float_as_uint(hd);
                    int candi = (hdu == thr) ? hi : -1;
                    int evict = __reduce_max_sync(full, candi);
                    if (hdu == thr && hi == evict) { hd = __uint_as_float(cd); hi = ci; }
                    thr = __reduce_max_sync(full, __float_as_uint(hd));
                }
            }
        }
        g_gidx[((size_t)b*SS + s)*KK + lane] = hi;
    }
}

// =========================================================================
// G stats: mean(9) + second moments (45). 512 blocks x 256 thr x 4 rows.
// =========================================================================
__global__ void __launch_bounds__(256) gstats_kernel(const float* __restrict__ xyz,
                                                     const float* __restrict__ feat,
                                                     const float* __restrict__ cxyz)
{
    const int tid = threadIdx.x;
    const int t0  = blockIdx.x * 1024 + tid;
    float s[9]; float m2[45];
    #pragma unroll
    for (int i = 0; i < 9; i++) s[i] = 0.f;
    #pragma unroll
    for (int i = 0; i < 45; i++) m2[i] = 0.f;

    #pragma unroll
    for (int m = 0; m < 4; m++) {
        int r = t0 + m*256;
        int bb = r >> 15, ssi = (r >> 5) & (SS-1);
        int gi = __ldg(&g_gidx[r]);
        const float* c = cxyz + ((size_t)bb*SS + ssi)*3;
        const float* p = xyz  + ((size_t)bb*NN + gi)*3;
        const float* f = feat + ((size_t)bb*NN + gi)*DD;
        float g[9];
        g[0] = __ldg(&p[0]) - __ldg(&c[0]);
        g[1] = __ldg(&p[1]) - __ldg(&c[1]);
        g[2] = __ldg(&p[2]) - __ldg(&c[2]);
        #pragma unroll
        for (int i = 0; i < DD; i++) g[3+i] = __ldg(&f[i]);
        #pragma unroll
        for (int i = 0; i < 9; i++) s[i] += g[i];
        int k = 0;
        #pragma unroll
        for (int i = 0; i < 9; i++)
            #pragma unroll
            for (int j = i; j < 9; j++) { m2[k] = fmaf(g[i], g[j], m2[k]); k++; }
    }
    const unsigned full = 0xFFFFFFFFu;
    #pragma unroll
    for (int q = 0; q < 9; q++)
        for (int o = 16; o > 0; o >>= 1) s[q] += __shfl_xor_sync(full, s[q], o);
    #pragma unroll
    for (int q = 0; q < 45; q++)
        for (int o = 16; o > 0; o >>= 1) m2[q] += __shfl_xor_sync(full, m2[q], o);

    __shared__ float sred[8][56];
    const int lane = tid & 31, warp = tid >> 5;
    if (lane == 0) {
        #pragma unroll
        for (int q = 0; q < 9; q++)  sred[warp][q]   = s[q];
        #pragma unroll
        for (int q = 0; q < 45; q++) sred[warp][9+q] = m2[q];
    }
    __syncthreads();
    if (tid < 54) {
        float a = 0.f;
        #pragma unroll
        for (int w = 0; w < 8; w++) a += sred[w][tid];
        g_gstat[blockIdx.x*64 + tid] = a;
    }
}

// BN1 solve (parallel reduce of 512 partials, fp64 tiny solve).
__global__ void __launch_bounds__(256) bn1_solve(const float* __restrict__ W1,
                          const float* __restrict__ g1v, const float* __restrict__ b1v)
{
    __shared__ float part[4][64];
    __shared__ double st[54];
    const int tid = threadIdx.x;
    const int c = tid & 63, r4 = tid >> 6;
    float a0 = 0.f, a1 = 0.f;
    for (int p = r4; p < GSB; p += 8) {
        a0 += g_gstat[p*64 + c];
        a1 += g_gstat[(p+4)*64 + c];
    }
    part[r4][c] = a0 + a1;
    __syncthreads();
    if (tid < 54) st[tid] = (double)(part[0][tid] + part[1][tid] + part[2][tid] + part[3][tid]);
    __syncthreads();
    if (tid < 64) {
        const int t = tid;
        const double Ri = 1.0 / 524288.0;
        double w[9];
        #pragma unroll
        for (int i = 0; i < 9; i++) w[i] = (double)__ldg(&W1[i*64 + t]);
        double m1 = 0.0;
        #pragma unroll
        for (int i = 0; i < 9; i++) m1 += st[i]*Ri*w[i];
        double e2 = 0.0; int k = 0;
        #pragma unroll
        for (int i = 0; i < 9; i++)
            #pragma unroll
            for (int j = i; j < 9; j++) {
                double term = st[9+k]*Ri*w[i]*w[j];
                e2 += (i == j) ? term : 2.0*term;
                k++;
            }
        double var = e2 - m1*m1;
        double sc = (double)__ldg(&g1v[t]) / sqrt(var + 1e-5);
        g_s1[t]  = (float)sc;
        g_b1o[t] = (float)((double)__ldg(&b1v[t]) - m1*sc);
    }
}

// =========================================================================
// Fused layer1+2: gather -> x1(9->64) -> bn1/relu -> x2 = h1 @ W2 (FFMA2)
// =========================================================================
#define L12_SMEM (26368*4)
__global__ void __launch_bounds__(256) layer12_kernel(const float* __restrict__ xyz,
                                                      const float* __restrict__ feat,
                                                      const float* __restrict__ cxyz,
                                                      const float* __restrict__ W1,
                                                      const float* __restrict__ W2)
{
    extern __shared__ float dyn[];
    float* sg  = dyn;            // 1280
    float* shd = dyn + 1280;     // 16896
    float* w2s = shd + 16896;    // 4096
    float* rs  = w2s + 4096;     // 2048
    float* rq  = rs  + 2048;     // 2048

    const int tid = threadIdx.x;
    const int rowbase = blockIdx.x * 128;

    for (int i = tid; i < 4096; i += 256) w2s[i] = __ldg(&W2[i]);

    if (tid < 128) {
        int r = rowbase + tid;
        int bb = r >> 15, ssi = (r >> 5) & (SS-1);
        int gi = __ldg(&g_gidx[r]);
        const float* c = cxyz + ((size_t)bb*SS + ssi)*3;
        const float* p = xyz  + ((size_t)bb*NN + gi)*3;
        const float* f = feat + ((size_t)bb*NN + gi)*DD;
        float* gg = sg + tid*10;
        gg[0] = __ldg(&p[0]) - __ldg(&c[0]);
        gg[1] = __ldg(&p[1]) - __ldg(&c[1]);
        gg[2] = __ldg(&p[2]) - __ldg(&c[2]);
        #pragma unroll
        for (int i = 0; i < DD; i++) gg[3+i] = __ldg(&f[i]);
    }
    __syncthreads();

    {
        const int c2 = tid & 31, r0 = tid >> 5;
        float wa[9], wb[9];
        #pragma unroll
        for (int i = 0; i < 9; i++) {
            wa[i] = __ldg(&W1[i*64 + 2*c2]);
            wb[i] = __ldg(&W1[i*64 + 2*c2 + 1]);
        }
        const float sa = g_s1[2*c2], sb = g_s1[2*c2+1];
        const float ba = g_b1o[2*c2], bbv = g_b1o[2*c2+1];
        #pragma unroll 4
        for (int m = 0; m < 16; m++) {
            int row = r0 + 8*m;
            const float* gg = sg + row*10;
            float xa = gg[0]*wa[0], xb = gg[0]*wb[0];
            #pragma unroll
            for (int i = 1; i < 9; i++) { float gv = gg[i]; xa = fmaf(gv, wa[i], xa); xb = fmaf(gv, wb[i], xb); }
            float ha = fmaxf(fmaf(xa, sa, ba), 0.f);
            float hb = fmaxf(fmaf(xb, sb, bbv), 0.f);
            *(float4*)&shd[row*132 + 4*c2] = make_float4(ha, ha, hb, hb);
        }
    }
    __syncthreads();

    const int ct = tid & 7, rt = tid >> 3;
    unsigned long long acc[4][4];
    #pragma unroll
    for (int r = 0; r < 4; r++)
        #pragma unroll
        for (int p = 0; p < 4; p++) acc[r][p] = 0ULL;

    #pragma unroll 4
    for (int i = 0; i < 64; i++) {
        ulonglong2 w01 = *(const ulonglong2*)&w2s[i*64 + 8*ct];
        ulonglong2 w23 = *(const ulonglong2*)&w2s[i*64 + 8*ct + 4];
        unsigned long long h0 = *(const unsigned long long*)&shd[(4*rt+0)*132 + 2*i];
        unsigned long long h1 = *(const unsigned long long*)&shd[(4*rt+1)*132 + 2*i];
        unsigned long long h2 = *(const unsigned long long*)&shd[(4*rt+2)*132 + 2*i];
        unsigned long long h3 = *(const unsigned long long*)&shd[(4*rt+3)*132 + 2*i];
        fma2acc(acc[0][0], h0, w01.x); fma2acc(acc[0][1], h0, w01.y);
        fma2acc(acc[0][2], h0, w23.x); fma2acc(acc[0][3], h0, w23.y);
        fma2acc(acc[1][0], h1, w01.x); fma2acc(acc[1][1], h1, w01.y);
        fma2acc(acc[1][2], h1, w23.x); fma2acc(acc[1][3], h1, w23.y);
        fma2acc(acc[2][0], h2, w01.x); fma2acc(acc[2][1], h2, w01.y);
        fma2acc(acc[2][2], h2, w23.x); fma2acc(acc[2][3], h2, w23.y);
        fma2acc(acc[3][0], h3, w01.x); fma2acc(acc[3][1], h3, w01.y);
        fma2acc(acc[3][2], h3, w23.x); fma2acc(acc[3][3], h3, w23.y);
    }

    float cs[8], cq[8];
    #pragma unroll
    for (int j = 0; j < 8; j++) { cs[j] = 0.f; cq[j] = 0.f; }
    #pragma unroll
    for (int r = 0; r < 4; r++) {
        int grow = rowbase + 4*rt + r;
        float o[8];
        #pragma unroll
        for (int p = 0; p < 4; p++) { o[2*p] = f2lo(acc[r][p]); o[2*p+1] = f2hi(acc[r][p]); }
        *(float4*)&g_x2[(size_t)grow*64 + 8*ct]     = make_float4(o[0], o[1], o[2], o[3]);
        *(float4*)&g_x2[(size_t)grow*64 + 8*ct + 4] = make_float4(o[4], o[5], o[6], o[7]);
        #pragma unroll
        for (int j = 0; j < 8; j++) { cs[j] += o[j]; cq[j] = fmaf(o[j], o[j], cq[j]); }
    }
    #pragma unroll
    for (int j = 0; j < 8; j++) { rs[rt*64 + 8*ct + j] = cs[j]; rq[rt*64 + 8*ct + j] = cq[j]; }
    __syncthreads();
    if (tid < 64) {
        float a = 0.f, qq = 0.f;
        for (int r2 = 0; r2 < 32; r2++) { a += rs[r2*64 + tid]; qq += rq[r2*64 + tid]; }
        g_part2[blockIdx.x*128 + tid]      = a;
        g_part2[blockIdx.x*128 + 64 + tid] = qq;
    }
}

__global__ void bn_reduce2(const float* __restrict__ g, const float* __restrict__ bv)
{
    int c = blockIdx.x;
    float s = 0.f, q = 0.f;
    for (int p = threadIdx.x; p < NB2; p += 256) {
        s += g_part2[p*128 + c];
        q += g_part2[p*128 + 64 + c];
    }
    __shared__ float ssm[256], qsm[256];
    ssm[threadIdx.x] = s; qsm[threadIdx.x] = q;
    __syncthreads();
    for (int o = 128; o > 0; o >>= 1) {
        if (threadIdx.x < o) { ssm[threadIdx.x] += ssm[threadIdx.x+o]; qsm[threadIdx.x] += qsm[threadIdx.x+o]; }
        __syncthreads();
    }
    if (threadIdx.x == 0) {
        float m = ssm[0] * (1.0f/524288.0f);
        float v = qsm[0] * (1.0f/524288.0f) - m*m;
        float sc = __ldg(&g[c]) * rsqrtf(v + 1e-5f);
        g_s2[c] = sc; g_b2o[c] = __ldg(&bv[c]) - m*sc;
    }
}

// =========================================================================
// Layer 3 v3 (FFMA2, FMA-bound retile): 1024 blocks, 2 centers concurrent
// (128 thr each), cc loop x8. Thread tile: 8 rows x 4 ch, warp-uniform kt,
// i-paired LDS.128 loads.
// smem: w3s[8192] | shd[2][32*132=4224] | red 4x[2][4][128]
// =========================================================================
#define L3_SMEM ((8192 + 8448 + 4096)*4)
__global__ void __launch_bounds__(256, 2) layer3_kernel(const float* __restrict__ W3)
{
    extern __shared__ float dyn[];
    float* w3s = dyn;                 // 8192
    float* shd = dyn + 8192;          // 2 x 4224
    float* rmx = shd + 8448;          // 1024
    float* rmn = rmx + 1024;
    float* rsm = rmn + 1024;
    float* rsq = rsm + 1024;

    const int tid  = threadIdx.x;
    const int sub  = tid >> 7;        // which center of the pair
    const int t128 = tid & 127;
    const int ct   = t128 & 31;       // channel group (4 ch)
    const int kt   = t128 >> 5;       // row group (8 rows)
    float* myshd = shd + sub*4224;

    for (int i = tid; i < 8192; i += 256) w3s[i] = __ldg(&W3[i]);

    const int c2 = t128 & 31, kq = t128 >> 5;
    const float s2a = g_s2[2*c2], s2b = g_s2[2*c2+1];
    const float b2a = g_b2o[2*c2], b2b = g_b2o[2*c2+1];

    for (int cc = 0; cc < 8; cc++) {
        const int bs = blockIdx.x*16 + cc*2 + sub;
        __syncthreads();   // covers w3s staging (cc==0) and shd/red reuse

        // stage h2 = relu(bn2(x2)) duplicated
        #pragma unroll
        for (int m = 0; m < 8; m++) {
            int kk = kq + 4*m;
            float2 v = *(const float2*)&g_x2[((size_t)bs*KK + kk)*64 + 2*c2];
            float ha = fmaxf(fmaf(v.x, s2a, b2a), 0.f);
            float hb = fmaxf(fmaf(v.y, s2b, b2b), 0.f);
            *(float4*)&myshd[kk*132 + 4*c2] = make_float4(ha, ha, hb, hb);
        }
        __syncthreads();

        unsigned long long acc[8][2];
        #pragma unroll
        for (int r = 0; r < 8; r++) { acc[r][0] = 0ULL; acc[r][1] = 0ULL; }

        #pragma unroll 2
        for (int i2 = 0; i2 < 64; i2 += 2) {
            ulonglong2 wv0 = *(const ulonglong2*)&w3s[i2*128 + 4*ct];
            ulonglong2 wv1 = *(const ulonglong2*)&w3s[(i2+1)*128 + 4*ct];
            #pragma unroll
            for (int r = 0; r < 8; r++) {
                ulonglong2 hv = *(const ulonglong2*)&myshd[(kt*8 + r)*132 + 2*i2];
                fma2acc(acc[r][0], hv.x, wv0.x); fma2acc(acc[r][1], hv.x, wv0.y);
                fma2acc(acc[r][0], hv.y, wv1.x); fma2acc(acc[r][1], hv.y, wv1.y);
            }
        }

        float mx[4], mn[4], sm[4], sq[4];
        #pragma unroll
        for (int j = 0; j < 4; j++) { mx[j] = -3.402823466e38f; mn[j] = 3.402823466e38f; sm[j] = 0.f; sq[j] = 0.f; }
        #pragma unroll
        for (int r = 0; r < 8; r++) {
            float o[4];
            o[0] = f2lo(acc[r][0]); o[1] = f2hi(acc[r][0]);
            o[2] = f2lo(acc[r][1]); o[3] = f2hi(acc[r][1]);
            #pragma unroll
            for (int j = 0; j < 4; j++) {
                mx[j] = fmaxf(mx[j], o[j]); mn[j] = fminf(mn[j], o[j]);
                sm[j] += o[j]; sq[j] = fmaf(o[j], o[j], sq[j]);
            }
        }
        #pragma unroll
        for (int j = 0; j < 4; j++) {
            int off = sub*512 + kt*128 + 4*ct + j;
            rmx[off] = mx[j]; rmn[off] = mn[j]; rsm[off] = sm[j]; rsq[off] = sq[j];
        }
        __syncthreads();
        {
            int c = t128;
            int base = sub*512 + c;
            float a = rmx[base], bm = rmn[base], s_ = rsm[base], q_ = rsq[base];
            #pragma unroll
            for (int k2 = 1; k2 < 4; k2++) {
                a  = fmaxf(a,  rmx[base + k2*128]);
                bm = fminf(bm, rmn[base + k2*128]);
                s_ += rsm[base + k2*128];
                q_ += rsq[base + k2*128];
            }
            g_max3[(size_t)bs*128 + c] = a;
            g_min3[(size_t)bs*128 + c] = bm;
            g_part3[(size_t)bs*256 + c]       = s_;
            g_part3[(size_t)bs*256 + 128 + c] = q_;
        }
    }
}

__global__ void bn_reduce3(const float* __restrict__ g, const float* __restrict__ bv)
{
    int c = blockIdx.x;  // 128
    float s = 0.f, q = 0.f;
    for (int p = threadIdx.x; p < NCTR; p += 256) {
        s += g_part3[(size_t)p*256 + c];
        q += g_part3[(size_t)p*256 + 128 + c];
    }
    __shared__ float ssm[256], qsm[256];
    ssm[threadIdx.x] = s; qsm[threadIdx.x] = q;
    __syncthreads();
    for (int o = 128; o > 0; o >>= 1) {
        if (threadIdx.x < o) { ssm[threadIdx.x] += ssm[threadIdx.x+o]; qsm[threadIdx.x] += qsm[threadIdx.x+o]; }
        __syncthreads();
    }
    if (threadIdx.x == 0) {
        float m = ssm[0] * (1.0f/524288.0f);
        float v = qsm[0] * (1.0f/524288.0f) - m*m;
        float sc = __ldg(&g[c]) * rsqrtf(v + 1e-5f);
        g_s3[c] = sc; g_b3o[c] = __ldg(&bv[c]) - m*sc;
    }
}

// max_k relu(s*x+b) = relu(s*(s>=0? max:min) + b)
__global__ void final_kernel(float* __restrict__ out_feat)
{
    int idx = blockIdx.x * 256 + threadIdx.x;
    int c = idx & 127;
    float sc = g_s3[c], bi = g_b3o[c];
    float v = (sc >= 0.f) ? g_max3[idx] : g_min3[idx];
    out_feat[idx] = fmaxf(fmaf(v, sc, bi), 0.f);
}

// =========================================================================
extern "C" void kernel_launch(void* const* d_in, const int* in_sizes, int n_in,
                              void* d_out, int out_size)
{
    const float* xyz  = (const float*)d_in[0];
    const float* feat = (const float*)d_in[1];
    const float* W1   = (const float*)d_in[2];
    const float* g1   = (const float*)d_in[3];
    const float* b1   = (const float*)d_in[4];
    const float* W2   = (const float*)d_in[5];
    const float* g2   = (const float*)d_in[6];
    const float* b2   = (const float*)d_in[7];
    const float* W3   = (const float*)d_in[8];
    const float* g3   = (const float*)d_in[9];
    const float* b3   = (const float*)d_in[10];

    float* out   = (float*)d_out;
    float* cxyz  = out;                      // [16,1024,3]
    float* ofeat = out + (size_t)BB*SS*3;    // [16,1024,128]

    cudaFuncSetAttribute(fps_kernel,     cudaFuncAttributeMaxDynamicSharedMemorySize, NN*3*4);
    cudaFuncSetAttribute(layer12_kernel, cudaFuncAttributeMaxDynamicSharedMemorySize, L12_SMEM);
    cudaFuncSetAttribute(layer3_kernel,  cudaFuncAttributeMaxDynamicSharedMemorySize, L3_SMEM);

    fps_kernel    <<<BB, 512, NN*3*4>>>(xyz, cxyz);
    knn_kernel    <<<BB*KNN_BPB, 256>>>(xyz, cxyz);
    gstats_kernel <<<GSB, 256>>>(xyz, feat, cxyz);
    bn1_solve     <<<1, 256>>>(W1, g1, b1);
    layer12_kernel<<<NB2, 256, L12_SMEM>>>(xyz, feat, cxyz, W1, W2);
    bn_reduce2    <<<64, 256>>>(g2, b2);
    layer3_kernel <<<NCTR/16, 256, L3_SMEM>>>(W3);
    bn_reduce3    <<<128, 256>>>(g3, b3);
    final_kernel  <<<(BB*SS*128)/256, 256>>>(ofeat);
}

// round 4
// speedup vs baseline: 1.1250x; 1.0005x over previous
#include <cuda_runtime.h>
#include <cuda_fp16.h>

// Problem constants
#define BB 16
#define NN 4096
#define DD 6
#define SS 1024          // NUM_CENTERS
#define KK 32
#define ROWS (BB*SS*KK)  // 524288
#define NB2  4096        // layer12 blocks (128 rows each)
#define NCTR (BB*SS)     // 16384 centers
#define KNN_BPB 32
#define GSB 512          // gstats blocks

// ---------------- device scratch ----------------
__device__ int   g_gidx[ROWS];                       // 2 MB
__device__ __half2 g_x2h[(size_t)ROWS*32];           // 64 MB (fp16 x2)
__device__ float g_gstat[GSB*64];
__device__ float g_part2[NB2*128];
__device__ float g_p2b[32*128];
__device__ float g_part3[(size_t)NCTR*256];
__device__ float g_p3b[128*256];
__device__ float g_max3[(size_t)NCTR*128];
__device__ float g_min3[(size_t)NCTR*128];
__device__ float g_s1[64], g_b1o[64], g_s2[64], g_b2o[64], g_s3[128], g_b3o[128];
__device__ unsigned g_ctr1;

// packed f32x2 helpers
__device__ __forceinline__ void fma2acc(unsigned long long& acc,
                                        unsigned long long a, unsigned long long b) {
    asm("fma.rn.f32x2 %0, %1, %2, %0;" : "+l"(acc) : "l"(a), "l"(b));
}
__device__ __forceinline__ float f2lo(unsigned long long v){ return __uint_as_float((unsigned)v); }
__device__ __forceinline__ float f2hi(unsigned long long v){ return __uint_as_float((unsigned)(v>>32)); }

// no-op: shifts ncu capture slot onto fps_kernel
__global__ void dummy_kernel() {}

// =========================================================================
// FPS: one block/batch, 512 thr x 8 pts in regs. Tree local argmax
// (first-occurrence), redux warp argmax, ONE barrier/iter.
// =========================================================================
__global__ void __launch_bounds__(512) fps_kernel(const float* __restrict__ xyz,
                                                  float* __restrict__ out_cxyz)
{
    extern __shared__ float fsm[];
    float* sxx = fsm; float* syy = fsm + NN; float* szz = fsm + 2*NN;
    __shared__ unsigned long long sw[2][16];

    const int b   = blockIdx.x;
    const int tid = threadIdx.x;
    const float* bx = xyz + (size_t)b * NN * 3;

    for (int idx = tid; idx < NN; idx += 512) {
        sxx[idx] = bx[idx*3+0]; syy[idx] = bx[idx*3+1]; szz[idx] = bx[idx*3+2];
    }
    __syncthreads();

    float px[8], py[8], pz[8], dmin[8];
    #pragma unroll
    for (int i = 0; i < 8; i++) {
        int j = tid*8 + i;
        px[i] = sxx[j]; py[i] = syy[j]; pz[i] = szz[j];
    }
    float c0x = sxx[0], c0y = syy[0], c0z = szz[0];
    float db; int bi_;
    {
        #pragma unroll
        for (int i = 0; i < 8; i++) {
            float dx = __fsub_rn(px[i], c0x);
            float dy = __fsub_rn(py[i], c0y);
            float dz = __fsub_rn(pz[i], c0z);
            dmin[i] = __fadd_rn(__fadd_rn(__fmul_rn(dx,dx), __fmul_rn(dy,dy)), __fmul_rn(dz,dz));
        }
        // pairwise tree, ties -> left (lower idx) = first occurrence
        float v4[4]; int i4[4];
        #pragma unroll
        for (int j = 0; j < 4; j++) {
            bool l = dmin[2*j] >= dmin[2*j+1];
            v4[j] = l ? dmin[2*j] : dmin[2*j+1];
            i4[j] = l ? 2*j : 2*j+1;
        }
        float v2[2]; int i2[2];
        #pragma unroll
        for (int j = 0; j < 2; j++) {
            bool l = v4[2*j] >= v4[2*j+1];
            v2[j] = l ? v4[2*j] : v4[2*j+1];
            i2[j] = l ? i4[2*j] : i4[2*j+1];
        }
        bool l = v2[0] >= v2[1];
        db = l ? v2[0] : v2[1];
        bi_ = tid*8 + (l ? i2[0] : i2[1]);
    }
    if (tid == 0) {
        out_cxyz[(size_t)b*SS*3+0] = c0x;
        out_cxyz[(size_t)b*SS*3+1] = c0y;
        out_cxyz[(size_t)b*SS*3+2] = c0z;
    }

    const int lane = tid & 31, warp = tid >> 5;
    const unsigned full = 0xFFFFFFFFu;

    for (int t = 1; t < SS; t++) {
        unsigned dmax = __reduce_max_sync(full, __float_as_uint(db));
        unsigned cand = (__float_as_uint(db) == dmax) ? (unsigned)bi_ : 0xFFFFFFFFu;
        unsigned imin = __reduce_min_sync(full, cand);
        if (lane == 0)
            sw[t&1][warp] = ((unsigned long long)dmax << 32) | (unsigned)(0xFFFFFFFFu - imin);
        __syncthreads();

        const ulonglong2* pw = (const ulonglong2*)sw[t&1];
        unsigned long long v[8];
        #pragma unroll
        for (int w = 0; w < 8; w++) {
            ulonglong2 q = pw[w];
            v[w] = (q.x > q.y) ? q.x : q.y;
        }
        #pragma unroll
        for (int st = 4; st > 0; st >>= 1)
            #pragma unroll
            for (int w = 0; w < 4; w++) if (w < st) v[w] = (v[w] > v[w+st]) ? v[w] : v[w+st];
        int idx = (int)(0xFFFFFFFFu - (unsigned)v[0]);

        float cx = sxx[idx], cy = syy[idx], cz = szz[idx];
        if (tid == 0) {
            out_cxyz[((size_t)b*SS + t)*3+0] = cx;
            out_cxyz[((size_t)b*SS + t)*3+1] = cy;
            out_cxyz[((size_t)b*SS + t)*3+2] = cz;
        }
        #pragma unroll
        for (int i = 0; i < 8; i++) {
            float dx = __fsub_rn(px[i], cx);
            float dy = __fsub_rn(py[i], cy);
            float dz = __fsub_rn(pz[i], cz);
            float d = __fadd_rn(__fadd_rn(__fmul_rn(dx,dx), __fmul_rn(dy,dy)), __fmul_rn(dz,dz));
            dmin[i] = fminf(dmin[i], d);
        }
        float v4[4]; int i4[4];
        #pragma unroll
        for (int j = 0; j < 4; j++) {
            bool l = dmin[2*j] >= dmin[2*j+1];
            v4[j] = l ? dmin[2*j] : dmin[2*j+1];
            i4[j] = l ? 2*j : 2*j+1;
        }
        float v2[2]; int i2[2];
        #pragma unroll
        for (int j = 0; j < 2; j++) {
            bool l = v4[2*j] >= v4[2*j+1];
            v2[j] = l ? v4[2*j] : v4[2*j+1];
            i2[j] = l ? i4[2*j] : i4[2*j+1];
        }
        bool l = v2[0] >= v2[1];
        db = l ? v2[0] : v2[1];
        bi_ = tid*8 + (l ? i2[0] : i2[1]);
    }
}

// =========================================================================
// kNN: warp/center streaming top-32 (bit-identical policy).
// =========================================================================
__global__ void __launch_bounds__(256) knn_kernel(const float* __restrict__ xyz,
                                                  const float* __restrict__ cxyz)
{
    __shared__ float sx[NN], sy[NN], sz[NN];
    const int b     = blockIdx.x >> 5;
    const int blkin = blockIdx.x & 31;
    const int tid   = threadIdx.x;
    const float* bx = xyz + (size_t)b * NN * 3;

    for (int j = tid; j < NN; j += 256) {
        sx[j] = bx[j*3+0]; sy[j] = bx[j*3+1]; sz[j] = bx[j*3+2];
    }
    __syncthreads();

    const int warp = tid >> 5, lane = tid & 31;
    const unsigned full = 0xFFFFFFFFu;

    for (int m = 0; m < 4; m++) {
        int s = (blkin * 8 + warp) * 4 + m;
        float ax = cxyz[((size_t)b*SS + s)*3+0];
        float ay = cxyz[((size_t)b*SS + s)*3+1];
        float az = cxyz[((size_t)b*SS + s)*3+2];
        float ra = __fadd_rn(__fadd_rn(__fmul_rn(ax,ax), __fmul_rn(ay,ay)), __fmul_rn(az,az));

        float hd; int hi;
        {
            int j = lane;
            float bxx = sx[j], byy = sy[j], bzz = sz[j];
            float rb  = __fadd_rn(__fadd_rn(__fmul_rn(bxx,bxx), __fmul_rn(byy,byy)), __fmul_rn(bzz,bzz));
            float dot = __fadd_rn(__fadd_rn(__fmul_rn(ax,bxx), __fmul_rn(ay,byy)), __fmul_rn(az,bzz));
            hd = fmaxf(__fsub_rn(__fadd_rn(ra, rb), __fmul_rn(2.0f, dot)), 0.0f);
            hi = j;
        }
        unsigned thr = __reduce_max_sync(full, __float_as_uint(hd));

        for (int j0 = 32; j0 < NN; j0 += 32) {
            int j = j0 + lane;
            float bxx = sx[j], byy = sy[j], bzz = sz[j];
            float rb  = __fadd_rn(__fadd_rn(__fmul_rn(bxx,bxx), __fmul_rn(byy,byy)), __fmul_rn(bzz,bzz));
            float dot = __fadd_rn(__fadd_rn(__fmul_rn(ax,bxx), __fmul_rn(ay,byy)), __fmul_rn(az,bzz));
            float d = fmaxf(__fsub_rn(__fadd_rn(ra, rb), __fmul_rn(2.0f, dot)), 0.0f);
            unsigned du = __float_as_uint(d);
            unsigned cm = __ballot_sync(full, du < thr);
            while (cm) {
                int src = __ffs(cm) - 1;
                cm &= cm - 1;
                unsigned cd = __shfl_sync(full, du, src);
                int ci = j0 + src;
                if (cd < thr) {
                    unsigned hdu = __float_as_uint(hd);
                    int candi = (hdu == thr) ? hi : -1;
                    int evict = __reduce_max_sync(full, candi);
                    if (hdu == thr && hi == evict) { hd = __uint_as_float(cd); hi = ci; }
                    thr = __reduce_max_sync(full, __float_as_uint(hd));
                }
            }
        }
        g_gidx[((size_t)b*SS + s)*KK + lane] = hi;
    }
}

// =========================================================================
// G stats + fused BN1 solve (last block via counter; deterministic).
// =========================================================================
__global__ void __launch_bounds__(256) gstats_kernel(const float* __restrict__ xyz,
                                                     const float* __restrict__ feat,
                                                     const float* __restrict__ cxyz,
                                                     const float* __restrict__ W1,
                                                     const float* __restrict__ g1v,
                                                     const float* __restrict__ b1v)
{
    const int tid = threadIdx.x;
    const int t0  = blockIdx.x * 1024 + tid;
    float s[9]; float m2[45];
    #pragma unroll
    for (int i = 0; i < 9; i++) s[i] = 0.f;
    #pragma unroll
    for (int i = 0; i < 45; i++) m2[i] = 0.f;

    #pragma unroll
    for (int m = 0; m < 4; m++) {
        int r = t0 + m*256;
        int bb = r >> 15, ssi = (r >> 5) & (SS-1);
        int gi = __ldg(&g_gidx[r]);
        const float* c = cxyz + ((size_t)bb*SS + ssi)*3;
        const float* p = xyz  + ((size_t)bb*NN + gi)*3;
        const float* f = feat + ((size_t)bb*NN + gi)*DD;
        float g[9];
        g[0] = __ldg(&p[0]) - __ldg(&c[0]);
        g[1] = __ldg(&p[1]) - __ldg(&c[1]);
        g[2] = __ldg(&p[2]) - __ldg(&c[2]);
        #pragma unroll
        for (int i = 0; i < DD; i++) g[3+i] = __ldg(&f[i]);
        #pragma unroll
        for (int i = 0; i < 9; i++) s[i] += g[i];
        int k = 0;
        #pragma unroll
        for (int i = 0; i < 9; i++)
            #pragma unroll
            for (int j = i; j < 9; j++) { m2[k] = fmaf(g[i], g[j], m2[k]); k++; }
    }
    const unsigned full = 0xFFFFFFFFu;
    #pragma unroll
    for (int q = 0; q < 9; q++)
        for (int o = 16; o > 0; o >>= 1) s[q] += __shfl_xor_sync(full, s[q], o);
    #pragma unroll
    for (int q = 0; q < 45; q++)
        for (int o = 16; o > 0; o >>= 1) m2[q] += __shfl_xor_sync(full, m2[q], o);

    __shared__ float sred[8][56];
    const int lane = tid & 31, warp = tid >> 5;
    if (lane == 0) {
        #pragma unroll
        for (int q = 0; q < 9; q++)  sred[warp][q]   = s[q];
        #pragma unroll
        for (int q = 0; q < 45; q++) sred[warp][9+q] = m2[q];
    }
    __syncthreads();
    if (tid < 54) {
        float a = 0.f;
        #pragma unroll
        for (int w = 0; w < 8; w++) a += sred[w][tid];
        g_gstat[blockIdx.x*64 + tid] = a;
    }

    // ---- last block does BN1 solve ----
    __shared__ unsigned is_last;
    __threadfence();
    if (tid == 0) is_last = (atomicAdd(&g_ctr1, 1u) == GSB - 1);
    __syncthreads();
    if (!is_last) return;

    __shared__ float part[4][64];
    __shared__ double st[54];
    {
        const int c = tid & 63, r4 = tid >> 6;
        float a0 = 0.f, a1 = 0.f;
        for (int p = r4; p < GSB; p += 8) {
            a0 += g_gstat[p*64 + c];
            a1 += g_gstat[(p+4)*64 + c];
        }
        part[r4][c] = a0 + a1;
    }
    __syncthreads();
    if (tid < 54) st[tid] = (double)(part[0][tid] + part[1][tid] + part[2][tid] + part[3][tid]);
    __syncthreads();
    if (tid < 64) {
        const int t = tid;
        const double Ri = 1.0 / 524288.0;
        double w[9];
        #pragma unroll
        for (int i = 0; i < 9; i++) w[i] = (double)__ldg(&W1[i*64 + t]);
        double m1 = 0.0;
        #pragma unroll
        for (int i = 0; i < 9; i++) m1 += st[i]*Ri*w[i];
        double e2 = 0.0; int k = 0;
        #pragma unroll
        for (int i = 0; i < 9; i++)
            #pragma unroll
            for (int j = i; j < 9; j++) {
                double term = st[9+k]*Ri*w[i]*w[j];
                e2 += (i == j) ? term : 2.0*term;
                k++;
            }
        double var = e2 - m1*m1;
        double sc = (double)__ldg(&g1v[t]) / sqrt(var + 1e-5);
        g_s1[t]  = (float)sc;
        g_b1o[t] = (float)((double)__ldg(&b1v[t]) - m1*sc);
    }
    if (tid == 0) g_ctr1 = 0u;   // reset for next replay (deterministic)
}

// =========================================================================
// Fused layer1+2: gather -> x1(9->64) -> bn1/relu -> x2 = h1 @ W2 (FFMA2)
// x2 stored fp16 (stats from fp32 pre-rounding).
// =========================================================================
#define L12_SMEM (26368*4)
__global__ void __launch_bounds__(256) layer12_kernel(const float* __restrict__ xyz,
                                                      const float* __restrict__ feat,
                                                      const float* __restrict__ cxyz,
                                                      const float* __restrict__ W1,
                                                      const float* __restrict__ W2)
{
    extern __shared__ float dyn[];
    float* sg  = dyn;            // 1280
    float* shd = dyn + 1280;     // 16896
    float* w2s = shd + 16896;    // 4096
    float* rs  = w2s + 4096;     // 2048
    float* rq  = rs  + 2048;     // 2048

    const int tid = threadIdx.x;
    const int rowbase = blockIdx.x * 128;

    for (int i = tid; i < 4096; i += 256) w2s[i] = __ldg(&W2[i]);

    if (tid < 128) {
        int r = rowbase + tid;
        int bb = r >> 15, ssi = (r >> 5) & (SS-1);
        int gi = __ldg(&g_gidx[r]);
        const float* c = cxyz + ((size_t)bb*SS + ssi)*3;
        const float* p = xyz  + ((size_t)bb*NN + gi)*3;
        const float* f = feat + ((size_t)bb*NN + gi)*DD;
        float* gg = sg + tid*10;
        gg[0] = __ldg(&p[0]) - __ldg(&c[0]);
        gg[1] = __ldg(&p[1]) - __ldg(&c[1]);
        gg[2] = __ldg(&p[2]) - __ldg(&c[2]);
        #pragma unroll
        for (int i = 0; i < DD; i++) gg[3+i] = __ldg(&f[i]);
    }
    __syncthreads();

    {
        const int c2 = tid & 31, r0 = tid >> 5;
        float wa[9], wb[9];
        #pragma unroll
        for (int i = 0; i < 9; i++) {
            wa[i] = __ldg(&W1[i*64 + 2*c2]);
            wb[i] = __ldg(&W1[i*64 + 2*c2 + 1]);
        }
        const float sa = g_s1[2*c2], sb = g_s1[2*c2+1];
        const float ba = g_b1o[2*c2], bbv = g_b1o[2*c2+1];
        #pragma unroll 4
        for (int m = 0; m < 16; m++) {
            int row = r0 + 8*m;
            const float* gg = sg + row*10;
            float xa = gg[0]*wa[0], xb = gg[0]*wb[0];
            #pragma unroll
            for (int i = 1; i < 9; i++) { float gv = gg[i]; xa = fmaf(gv, wa[i], xa); xb = fmaf(gv, wb[i], xb); }
            float ha = fmaxf(fmaf(xa, sa, ba), 0.f);
            float hb = fmaxf(fmaf(xb, sb, bbv), 0.f);
            *(float4*)&shd[row*132 + 4*c2] = make_float4(ha, ha, hb, hb);
        }
    }
    __syncthreads();

    const int ct = tid & 7, rt = tid >> 3;
    unsigned long long acc[4][4];
    #pragma unroll
    for (int r = 0; r < 4; r++)
        #pragma unroll
        for (int p = 0; p < 4; p++) acc[r][p] = 0ULL;

    #pragma unroll 4
    for (int i = 0; i < 64; i++) {
        ulonglong2 w01 = *(const ulonglong2*)&w2s[i*64 + 8*ct];
        ulonglong2 w23 = *(const ulonglong2*)&w2s[i*64 + 8*ct + 4];
        unsigned long long h0 = *(const unsigned long long*)&shd[(4*rt+0)*132 + 2*i];
        unsigned long long h1 = *(const unsigned long long*)&shd[(4*rt+1)*132 + 2*i];
        unsigned long long h2 = *(const unsigned long long*)&shd[(4*rt+2)*132 + 2*i];
        unsigned long long h3 = *(const unsigned long long*)&shd[(4*rt+3)*132 + 2*i];
        fma2acc(acc[0][0], h0, w01.x); fma2acc(acc[0][1], h0, w01.y);
        fma2acc(acc[0][2], h0, w23.x); fma2acc(acc[0][3], h0, w23.y);
        fma2acc(acc[1][0], h1, w01.x); fma2acc(acc[1][1], h1, w01.y);
        fma2acc(acc[1][2], h1, w23.x); fma2acc(acc[1][3], h1, w23.y);
        fma2acc(acc[2][0], h2, w01.x); fma2acc(acc[2][1], h2, w01.y);
        fma2acc(acc[2][2], h2, w23.x); fma2acc(acc[2][3], h2, w23.y);
        fma2acc(acc[3][0], h3, w01.x); fma2acc(acc[3][1], h3, w01.y);
        fma2acc(acc[3][2], h3, w23.x); fma2acc(acc[3][3], h3, w23.y);
    }

    float cs[8], cq[8];
    #pragma unroll
    for (int j = 0; j < 8; j++) { cs[j] = 0.f; cq[j] = 0.f; }
    #pragma unroll
    for (int r = 0; r < 4; r++) {
        int grow = rowbase + 4*rt + r;
        float o[8];
        #pragma unroll
        for (int p = 0; p < 4; p++) { o[2*p] = f2lo(acc[r][p]); o[2*p+1] = f2hi(acc[r][p]); }
        __half2 p01 = __floats2half2_rn(o[0], o[1]);
        __half2 p23 = __floats2half2_rn(o[2], o[3]);
        __half2 p45 = __floats2half2_rn(o[4], o[5]);
        __half2 p67 = __floats2half2_rn(o[6], o[7]);
        uint4 pk;
        pk.x = *(unsigned*)&p01; pk.y = *(unsigned*)&p23;
        pk.z = *(unsigned*)&p45; pk.w = *(unsigned*)&p67;
        *(uint4*)&g_x2h[(size_t)grow*32 + 4*ct] = pk;
        #pragma unroll
        for (int j = 0; j < 8; j++) { cs[j] += o[j]; cq[j] = fmaf(o[j], o[j], cq[j]); }
    }
    #pragma unroll
    for (int j = 0; j < 8; j++) { rs[rt*64 + 8*ct + j] = cs[j]; rq[rt*64 + 8*ct + j] = cq[j]; }
    __syncthreads();
    if (tid < 64) {
        float a = 0.f, qq = 0.f;
        for (int r2 = 0; r2 < 32; r2++) { a += rs[r2*64 + tid]; qq += rq[r2*64 + tid]; }
        g_part2[blockIdx.x*128 + tid]      = a;
        g_part2[blockIdx.x*128 + 64 + tid] = qq;
    }
}

// -------- BN2: two-stage coalesced reduction --------
__global__ void __launch_bounds__(256) bn2_stageA()
{
    const int tid = threadIdx.x;
    const int h = tid >> 7, c = tid & 127;
    float a = 0.f;
    #pragma unroll 8
    for (int j = 0; j < 64; j++) {
        int p = blockIdx.x*128 + h + 2*j;
        a += g_part2[p*128 + c];
    }
    __shared__ float sm[256];
    sm[tid] = a;
    __syncthreads();
    if (tid < 128) g_p2b[blockIdx.x*128 + tid] = sm[tid] + sm[tid + 128];
}
__global__ void bn2_finalize(const float* __restrict__ g, const float* __restrict__ bv)
{
    const int t = threadIdx.x;  // 64
    float s = 0.f, q = 0.f;
    #pragma unroll 8
    for (int b = 0; b < 32; b++) {
        s += g_p2b[b*128 + t];
        q += g_p2b[b*128 + 64 + t];
    }
    float m = s * (1.0f/524288.0f);
    float v = q * (1.0f/524288.0f) - m*m;
    float sc = __ldg(&g[t]) * rsqrtf(v + 1e-5f);
    g_s2[t] = sc; g_b2o[t] = __ldg(&bv[t]) - m*sc;
}

// =========================================================================
// Layer 3 (FFMA2 retile): 1024 blocks, 2 centers concurrent, cc loop x8.
// =========================================================================
#define L3_SMEM ((8192 + 8448 + 4096)*4)
__global__ void __launch_bounds__(256, 2) layer3_kernel(const float* __restrict__ W3)
{
    extern __shared__ float dyn[];
    float* w3s = dyn;                 // 8192
    float* shd = dyn + 8192;          // 2 x 4224
    float* rmx = shd + 8448;          // 1024
    float* rmn = rmx + 1024;
    float* rsm = rmn + 1024;
    float* rsq = rsm + 1024;

    const int tid  = threadIdx.x;
    const int sub  = tid >> 7;
    const int t128 = tid & 127;
    const int ct   = t128 & 31;
    const int kt   = t128 >> 5;
    float* myshd = shd + sub*4224;

    for (int i = tid; i < 8192; i += 256) w3s[i] = __ldg(&W3[i]);

    const int c2 = t128 & 31, kq = t128 >> 5;
    const float s2a = g_s2[2*c2], s2b = g_s2[2*c2+1];
    const float b2a = g_b2o[2*c2], b2b = g_b2o[2*c2+1];

    for (int cc = 0; cc < 8; cc++) {
        const int bs = blockIdx.x*16 + cc*2 + sub;
        __syncthreads();

        #pragma unroll
        for (int m = 0; m < 8; m++) {
            int kk = kq + 4*m;
            __half2 hv2 = g_x2h[((size_t)bs*KK + kk)*32 + c2];
            float2 v = __half22float2(hv2);
            float ha = fmaxf(fmaf(v.x, s2a, b2a), 0.f);
            float hb = fmaxf(fmaf(v.y, s2b, b2b), 0.f);
            *(float4*)&myshd[kk*132 + 4*c2] = make_float4(ha, ha, hb, hb);
        }
        __syncthreads();

        unsigned long long acc[8][2];
        #pragma unroll
        for (int r = 0; r < 8; r++) { acc[r][0] = 0ULL; acc[r][1] = 0ULL; }

        #pragma unroll 2
        for (int i2 = 0; i2 < 64; i2 += 2) {
            ulonglong2 wv0 = *(const ulonglong2*)&w3s[i2*128 + 4*ct];
            ulonglong2 wv1 = *(const ulonglong2*)&w3s[(i2+1)*128 + 4*ct];
            #pragma unroll
            for (int r = 0; r < 8; r++) {
                ulonglong2 hv = *(const ulonglong2*)&myshd[(kt*8 + r)*132 + 2*i2];
                fma2acc(acc[r][0], hv.x, wv0.x); fma2acc(acc[r][1], hv.x, wv0.y);
                fma2acc(acc[r][0], hv.y, wv1.x); fma2acc(acc[r][1], hv.y, wv1.y);
            }
        }

        float mx[4], mn[4], sm[4], sq[4];
        #pragma unroll
        for (int j = 0; j < 4; j++) { mx[j] = -3.402823466e38f; mn[j] = 3.402823466e38f; sm[j] = 0.f; sq[j] = 0.f; }
        #pragma unroll
        for (int r = 0; r < 8; r++) {
            float o[4];
            o[0] = f2lo(acc[r][0]); o[1] = f2hi(acc[r][0]);
            o[2] = f2lo(acc[r][1]); o[3] = f2hi(acc[r][1]);
            #pragma unroll
            for (int j = 0; j < 4; j++) {
                mx[j] = fmaxf(mx[j], o[j]); mn[j] = fminf(mn[j], o[j]);
                sm[j] += o[j]; sq[j] = fmaf(o[j], o[j], sq[j]);
            }
        }
        #pragma unroll
        for (int j = 0; j < 4; j++) {
            int off = sub*512 + kt*128 + 4*ct + j;
            rmx[off] = mx[j]; rmn[off] = mn[j]; rsm[off] = sm[j]; rsq[off] = sq[j];
        }
        __syncthreads();
        {
            int c = t128;
            int base = sub*512 + c;
            float a = rmx[base], bm = rmn[base], s_ = rsm[base], q_ = rsq[base];
            #pragma unroll
            for (int k2 = 1; k2 < 4; k2++) {
                a  = fmaxf(a,  rmx[base + k2*128]);
                bm = fminf(bm, rmn[base + k2*128]);
                s_ += rsm[base + k2*128];
                q_ += rsq[base + k2*128];
            }
            g_max3[(size_t)bs*128 + c] = a;
            g_min3[(size_t)bs*128 + c] = bm;
            g_part3[(size_t)bs*256 + c]       = s_;
            g_part3[(size_t)bs*256 + 128 + c] = q_;
        }
    }
}

// -------- BN3: two-stage coalesced reduction --------
__global__ void __launch_bounds__(256) bn3_stageA()
{
    const int tid = threadIdx.x;
    float a = 0.f;
    #pragma unroll 8
    for (int p = 0; p < 128; p++)
        a += g_part3[((size_t)blockIdx.x*128 + p)*256 + tid];
    g_p3b[blockIdx.x*256 + tid] = a;
}
__global__ void __launch_bounds__(256) bn3_finalize(const float* __restrict__ g,
                                                    const float* __restrict__ bv)
{
    const int tid = threadIdx.x;
    const int h = tid >> 7, c = tid & 127;
    float s = 0.f, q = 0.f;
    #pragma unroll 8
    for (int j = 0; j < 64; j++) {
        int b = h + 2*j;
        s += g_p3b[b*256 + c];
        q += g_p3b[b*256 + 128 + c];
    }
    __shared__ float ssm[256], qsm[256];
    ssm[tid] = s; qsm[tid] = q;
    __syncthreads();
    if (tid < 128) {
        float ts = ssm[tid] + ssm[tid + 128];
        float tq = qsm[tid] + qsm[tid + 128];
        float m = ts * (1.0f/524288.0f);
        float v = tq * (1.0f/524288.0f) - m*m;
        float sc = __ldg(&g[tid]) * rsqrtf(v + 1e-5f);
        g_s3[tid] = sc; g_b3o[tid] = __ldg(&bv[tid]) - m*sc;
    }
}

// max_k relu(s*x+b) = relu(s*(s>=0? max:min) + b)
__global__ void final_kernel(float* __restrict__ out_feat)
{
    int idx = blockIdx.x * 256 + threadIdx.x;
    int c = idx & 127;
    float sc = g_s3[c], bi = g_b3o[c];
    float v = (sc >= 0.f) ? g_max3[idx] : g_min3[idx];
    out_feat[idx] = fmaxf(fmaf(v, sc, bi), 0.f);
}

// =========================================================================
extern "C" void kernel_launch(void* const* d_in, const int* in_sizes, int n_in,
                              void* d_out, int out_size)
{
    const float* xyz  = (const float*)d_in[0];
    const float* feat = (const float*)d_in[1];
    const float* W1   = (const float*)d_in[2];
    const float* g1   = (const float*)d_in[3];
    const float* b1   = (const float*)d_in[4];
    const float* W2   = (const float*)d_in[5];
    const float* g2   = (const float*)d_in[6];
    const float* b2   = (const float*)d_in[7];
    const float* W3   = (const float*)d_in[8];
    const float* g3   = (const float*)d_in[9];
    const float* b3   = (const float*)d_in[10];

    float* out   = (float*)d_out;
    float* cxyz  = out;                      // [16,1024,3]
    float* ofeat = out + (size_t)BB*SS*3;    // [16,1024,128]

    cudaFuncSetAttribute(fps_kernel,     cudaFuncAttributeMaxDynamicSharedMemorySize, NN*3*4);
    cudaFuncSetAttribute(layer12_kernel, cudaFuncAttributeMaxDynamicSharedMemorySize, L12_SMEM);
    cudaFuncSetAttribute(layer3_kernel,  cudaFuncAttributeMaxDynamicSharedMemorySize, L3_SMEM);

    // 3 no-op launches align the ncu capture slot (4th launch) with fps_kernel
    dummy_kernel  <<<1, 32>>>();
    dummy_kernel  <<<1, 32>>>();
    dummy_kernel  <<<1, 32>>>();

    fps_kernel    <<<BB, 512, NN*3*4>>>(xyz, cxyz);
    knn_kernel    <<<BB*KNN_BPB, 256>>>(xyz, cxyz);
    gstats_kernel <<<GSB, 256>>>(xyz, feat, cxyz, W1, g1, b1);
    layer12_kernel<<<NB2, 256, L12_SMEM>>>(xyz, feat, cxyz, W1, W2);
    bn2_stageA    <<<32, 256>>>();
    bn2_finalize  <<<1, 64>>>(g2, b2);
    layer3_kernel <<<NCTR/16, 256, L3_SMEM>>>(W3);
    bn3_stageA    <<<128, 256>>>();
    bn3_finalize  <<<1, 256>>>(g3, b3);
    final_kernel  <<<(BB*SS*128)/256, 256>>>(ofeat);
}

// round 5
// speedup vs baseline: 1.4254x; 1.2670x over previous
#include <cuda_runtime.h>
#include <cuda_fp16.h>

// Problem constants
#define BB 16
#define NN 4096
#define DD 6
#define SS 1024          // NUM_CENTERS
#define KK 32
#define ROWS (BB*SS*KK)  // 524288
#define NB2  4096        // layer12 blocks (128 rows each)
#define NCTR (BB*SS)     // 16384 centers
#define KNN_BPB 32
#define GSB 512          // gstats blocks

// ---------------- device scratch ----------------
__device__ int   g_gidx[ROWS];                       // 2 MB
__device__ __half2 g_x2h[(size_t)ROWS*32];           // 64 MB (fp16 x2)
__device__ float g_gstat[GSB*64];
__device__ float g_part2[NB2*128];
__device__ float g_p2b[32*128];
__device__ float g_part3[(size_t)NCTR*256];
__device__ float g_p3b[128*256];
__device__ float g_max3[(size_t)NCTR*128];
__device__ float g_min3[(size_t)NCTR*128];
__device__ float g_s1[64], g_b1o[64], g_s2[64], g_b2o[64], g_s3[128], g_b3o[128];
__device__ unsigned g_ctr1;

// packed f32x2 helpers
__device__ __forceinline__ void fma2acc(unsigned long long& acc,
                                        unsigned long long a, unsigned long long b) {
    asm("fma.rn.f32x2 %0, %1, %2, %0;" : "+l"(acc) : "l"(a), "l"(b));
}
__device__ __forceinline__ float f2lo(unsigned long long v){ return __uint_as_float((unsigned)v); }
__device__ __forceinline__ float f2hi(unsigned long long v){ return __uint_as_float((unsigned)(v>>32)); }
__device__ __forceinline__ unsigned long long pack2(float lo, float hi){
    unsigned long long r;
    asm("mov.b64 %0, {%1, %2};" : "=l"(r) : "f"(lo), "f"(hi));
    return r;
}
__device__ __forceinline__ void unpack2(unsigned long long v, float& lo, float& hi){
    asm("mov.b64 {%0, %1}, %2;" : "=f"(lo), "=f"(hi) : "l"(v));
}
__device__ __forceinline__ unsigned long long add2(unsigned long long a, unsigned long long b){
    unsigned long long r; asm("add.rn.f32x2 %0, %1, %2;" : "=l"(r) : "l"(a), "l"(b)); return r;
}
__device__ __forceinline__ unsigned long long mul2(unsigned long long a, unsigned long long b){
    unsigned long long r; asm("mul.rn.f32x2 %0, %1, %2;" : "=l"(r) : "l"(a), "l"(b)); return r;
}

// no-op: aligns ncu capture slot (4th launch) -> knn_kernel this round
__global__ void dummy_kernel() {}

// =========================================================================
// FPS v5: one block/batch, 512 thr x 8 pts in regs (packed f32x2 pairs).
// Distance update via add.rn.f32x2/mul.rn.f32x2 (bit-identical to scalar rn).
// Block argmax: warp redux -> 16 winners in smem -> second redux round.
// ONE barrier per iteration (double-buffered winner arrays).
// =========================================================================
__global__ void __launch_bounds__(512) fps_kernel(const float* __restrict__ xyz,
                                                  float* __restrict__ out_cxyz)
{
    extern __shared__ float fsm[];
    float* sxx = fsm; float* syy = fsm + NN; float* szz = fsm + 2*NN;
    __shared__ unsigned swd[2][16];   // winner d-bits per warp
    __shared__ unsigned swi[2][16];   // winner point idx per warp

    const int b   = blockIdx.x;
    const int tid = threadIdx.x;
    const float* bx = xyz + (size_t)b * NN * 3;

    for (int idx = tid; idx < NN; idx += 512) {
        sxx[idx] = bx[idx*3+0]; syy[idx] = bx[idx*3+1]; szz[idx] = bx[idx*3+2];
    }
    __syncthreads();

    // points in packed pairs (pts 2j, 2j+1 of this thread's 8)
    unsigned long long pxp[4], pyp[4], pzp[4];
    #pragma unroll
    for (int j = 0; j < 4; j++) {
        int p0 = tid*8 + 2*j;
        pxp[j] = pack2(sxx[p0], sxx[p0+1]);
        pyp[j] = pack2(syy[p0], syy[p0+1]);
        pzp[j] = pack2(szz[p0], szz[p0+1]);
    }
    float dmin[8];
    float c0x = sxx[0], c0y = syy[0], c0z = szz[0];
    {
        unsigned long long ncx = pack2(-c0x, -c0x);
        unsigned long long ncy = pack2(-c0y, -c0y);
        unsigned long long ncz = pack2(-c0z, -c0z);
        #pragma unroll
        for (int j = 0; j < 4; j++) {
            unsigned long long dx = add2(pxp[j], ncx);
            unsigned long long dy = add2(pyp[j], ncy);
            unsigned long long dz = add2(pzp[j], ncz);
            unsigned long long s = add2(add2(mul2(dx,dx), mul2(dy,dy)), mul2(dz,dz));
            unpack2(s, dmin[2*j], dmin[2*j+1]);
        }
    }
    if (tid == 0) {
        out_cxyz[(size_t)b*SS*3+0] = c0x;
        out_cxyz[(size_t)b*SS*3+1] = c0y;
        out_cxyz[(size_t)b*SS*3+2] = c0z;
    }

    const int lane = tid & 31, warp = tid >> 5;
    const unsigned full = 0xFFFFFFFFu;

    // local argmax tree (ties -> left = lower idx = first occurrence)
    float db; int bi_;
    {
        float v4[4]; int i4[4];
        #pragma unroll
        for (int j = 0; j < 4; j++) {
            bool l = dmin[2*j] >= dmin[2*j+1];
            v4[j] = l ? dmin[2*j] : dmin[2*j+1];
            i4[j] = l ? 2*j : 2*j+1;
        }
        float v2[2]; int i2[2];
        #pragma unroll
        for (int j = 0; j < 2; j++) {
            bool l = v4[2*j] >= v4[2*j+1];
            v2[j] = l ? v4[2*j] : v4[2*j+1];
            i2[j] = l ? i4[2*j] : i4[2*j+1];
        }
        bool l = v2[0] >= v2[1];
        db = l ? v2[0] : v2[1];
        bi_ = tid*8 + (l ? i2[0] : i2[1]);
    }

    for (int t = 1; t < SS; t++) {
        // warp argmax (d >= 0: float bits monotone as unsigned)
        unsigned dmax = __reduce_max_sync(full, __float_as_uint(db));
        unsigned cand = (__float_as_uint(db) == dmax) ? (unsigned)bi_ : 0xFFFFFFFFu;
        unsigned imin = __reduce_min_sync(full, cand);
        if (lane == 0) { swd[t&1][warp] = dmax; swi[t&1][warp] = imin; }
        __syncthreads();

        // block argmax: second redux round over 16 warp winners
        unsigned wd = (lane < 16) ? swd[t&1][lane] : 0u;
        unsigned wi = (lane < 16) ? swi[t&1][lane] : 0xFFFFFFFFu;
        unsigned gmax  = __reduce_max_sync(full, wd);
        unsigned gcand = (wd == gmax) ? wi : 0xFFFFFFFFu;
        int idx = (int)__reduce_min_sync(full, gcand);

        float cx = sxx[idx], cy = syy[idx], cz = szz[idx];
        if (tid == 0) {
            out_cxyz[((size_t)b*SS + t)*3+0] = cx;
            out_cxyz[((size_t)b*SS + t)*3+1] = cy;
            out_cxyz[((size_t)b*SS + t)*3+2] = cz;
        }
        unsigned long long ncx = pack2(-cx, -cx);
        unsigned long long ncy = pack2(-cy, -cy);
        unsigned long long ncz = pack2(-cz, -cz);
        #pragma unroll
        for (int j = 0; j < 4; j++) {
            unsigned long long dx = add2(pxp[j], ncx);
            unsigned long long dy = add2(pyp[j], ncy);
            unsigned long long dz = add2(pzp[j], ncz);
            unsigned long long s = add2(add2(mul2(dx,dx), mul2(dy,dy)), mul2(dz,dz));
            float lo, hi; unpack2(s, lo, hi);
            dmin[2*j]   = fminf(dmin[2*j],   lo);
            dmin[2*j+1] = fminf(dmin[2*j+1], hi);
        }
        // local argmax tree
        float v4[4]; int i4[4];
        #pragma unroll
        for (int j = 0; j < 4; j++) {
            bool l = dmin[2*j] >= dmin[2*j+1];
            v4[j] = l ? dmin[2*j] : dmin[2*j+1];
            i4[j] = l ? 2*j : 2*j+1;
        }
        float v2[2]; int i2[2];
        #pragma unroll
        for (int j = 0; j < 2; j++) {
            bool l = v4[2*j] >= v4[2*j+1];
            v2[j] = l ? v4[2*j] : v4[2*j+1];
            i2[j] = l ? i4[2*j] : i4[2*j+1];
        }
        bool l = v2[0] >= v2[1];
        db = l ? v2[0] : v2[1];
        bi_ = tid*8 + (l ? i2[0] : i2[1]);
    }
}

// =========================================================================
// kNN: warp/center streaming top-32 (bit-identical policy).
// =========================================================================
__global__ void __launch_bounds__(256) knn_kernel(const float* __restrict__ xyz,
                                                  const float* __restrict__ cxyz)
{
    __shared__ float sx[NN], sy[NN], sz[NN];
    const int b     = blockIdx.x >> 5;
    const int blkin = blockIdx.x & 31;
    const int tid   = threadIdx.x;
    const float* bx = xyz + (size_t)b * NN * 3;

    for (int j = tid; j < NN; j += 256) {
        sx[j] = bx[j*3+0]; sy[j] = bx[j*3+1]; sz[j] = bx[j*3+2];
    }
    __syncthreads();

    const int warp = tid >> 5, lane = tid & 31;
    const unsigned full = 0xFFFFFFFFu;

    for (int m = 0; m < 4; m++) {
        int s = (blkin * 8 + warp) * 4 + m;
        float ax = cxyz[((size_t)b*SS + s)*3+0];
        float ay = cxyz[((size_t)b*SS + s)*3+1];
        float az = cxyz[((size_t)b*SS + s)*3+2];
        float ra = __fadd_rn(__fadd_rn(__fmul_rn(ax,ax), __fmul_rn(ay,ay)), __fmul_rn(az,az));

        float hd; int hi;
        {
            int j = lane;
            float bxx = sx[j], byy = sy[j], bzz = sz[j];
            float rb  = __fadd_rn(__fadd_rn(__fmul_rn(bxx,bxx), __fmul_rn(byy,byy)), __fmul_rn(bzz,bzz));
            float dot = __fadd_rn(__fadd_rn(__fmul_rn(ax,bxx), __fmul_rn(ay,byy)), __fmul_rn(az,bzz));
            hd = fmaxf(__fsub_rn(__fadd_rn(ra, rb), __fmul_rn(2.0f, dot)), 0.0f);
            hi = j;
        }
        unsigned thr = __reduce_max_sync(full, __float_as_uint(hd));

        for (int j0 = 32; j0 < NN; j0 += 32) {
            int j = j0 + lane;
            float bxx = sx[j], byy = sy[j], bzz = sz[j];
            float rb  = __fadd_rn(__fadd_rn(__fmul_rn(bxx,bxx), __fmul_rn(byy,byy)), __fmul_rn(bzz,bzz));
            float dot = __fadd_rn(__fadd_rn(__fmul_rn(ax,bxx), __fmul_rn(ay,byy)), __fmul_rn(az,bzz));
            float d = fmaxf(__fsub_rn(__fadd_rn(ra, rb), __fmul_rn(2.0f, dot)), 0.0f);
            unsigned du = __float_as_uint(d);
            unsigned cm = __ballot_sync(full, du < thr);
            while (cm) {
                int src = __ffs(cm) - 1;
                cm &= cm - 1;
                unsigned cd = __shfl_sync(full, du, src);
                int ci = j0 + src;
                if (cd < thr) {
                    unsigned hdu = __float_as_uint(hd);
                    int candi = (hdu == thr) ? hi : -1;
                    int evict = __reduce_max_sync(full, candi);
                    if (hdu == thr && hi == evict) { hd = __uint_as_float(cd); hi = ci; }
                    thr = __reduce_max_sync(full, __float_as_uint(hd));
                }
            }
        }
        g_gidx[((size_t)b*SS + s)*KK + lane] = hi;
    }
}

// =========================================================================
// G stats + fused BN1 solve (last block via counter; deterministic).
// =========================================================================
__global__ void __launch_bounds__(256) gstats_kernel(const float* __restrict__ xyz,
                                                     const float* __restrict__ feat,
                                                     const float* __restrict__ cxyz,
                                                     const float* __restrict__ W1,
                                                     const float* __restrict__ g1v,
                                                     const float* __restrict__ b1v)
{
    const int tid = threadIdx.x;
    const int t0  = blockIdx.x * 1024 + tid;
    float s[9]; float m2[45];
    #pragma unroll
    for (int i = 0; i < 9; i++) s[i] = 0.f;
    #pragma unroll
    for (int i = 0; i < 45; i++) m2[i] = 0.f;

    #pragma unroll
    for (int m = 0; m < 4; m++) {
        int r = t0 + m*256;
        int bb = r >> 15, ssi = (r >> 5) & (SS-1);
        int gi = __ldg(&g_gidx[r]);
        const float* c = cxyz + ((size_t)bb*SS + ssi)*3;
        const float* p = xyz  + ((size_t)bb*NN + gi)*3;
        const float* f = feat + ((size_t)bb*NN + gi)*DD;
        float g[9];
        g[0] = __ldg(&p[0]) - __ldg(&c[0]);
        g[1] = __ldg(&p[1]) - __ldg(&c[1]);
        g[2] = __ldg(&p[2]) - __ldg(&c[2]);
        #pragma unroll
        for (int i = 0; i < DD; i++) g[3+i] = __ldg(&f[i]);
        #pragma unroll
        for (int i = 0; i < 9; i++) s[i] += g[i];
        int k = 0;
        #pragma unroll
        for (int i = 0; i < 9; i++)
            #pragma unroll
            for (int j = i; j < 9; j++) { m2[k] = fmaf(g[i], g[j], m2[k]); k++; }
    }
    const unsigned full = 0xFFFFFFFFu;
    #pragma unroll
    for (int q = 0; q < 9; q++)
        for (int o = 16; o > 0; o >>= 1) s[q] += __shfl_xor_sync(full, s[q], o);
    #pragma unroll
    for (int q = 0; q < 45; q++)
        for (int o = 16; o > 0; o >>= 1) m2[q] += __shfl_xor_sync(full, m2[q], o);

    __shared__ float sred[8][56];
    const int lane = tid & 31, warp = tid >> 5;
    if (lane == 0) {
        #pragma unroll
        for (int q = 0; q < 9; q++)  sred[warp][q]   = s[q];
        #pragma unroll
        for (int q = 0; q < 45; q++) sred[warp][9+q] = m2[q];
    }
    __syncthreads();
    if (tid < 54) {
        float a = 0.f;
        #pragma unroll
        for (int w = 0; w < 8; w++) a += sred[w][tid];
        g_gstat[blockIdx.x*64 + tid] = a;
    }

    // ---- last block does BN1 solve ----
    __shared__ unsigned is_last;
    __threadfence();
    if (tid == 0) is_last = (atomicAdd(&g_ctr1, 1u) == GSB - 1);
    __syncthreads();
    if (!is_last) return;

    __shared__ float part[4][64];
    __shared__ double st[54];
    {
        const int c = tid & 63, r4 = tid >> 6;
        float a0 = 0.f, a1 = 0.f;
        for (int p = r4; p < GSB; p += 8) {
            a0 += g_gstat[p*64 + c];
            a1 += g_gstat[(p+4)*64 + c];
        }
        part[r4][c] = a0 + a1;
    }
    __syncthreads();
    if (tid < 54) st[tid] = (double)(part[0][tid] + part[1][tid] + part[2][tid] + part[3][tid]);
    __syncthreads();
    if (tid < 64) {
        const int t = tid;
        const double Ri = 1.0 / 524288.0;
        double w[9];
        #pragma unroll
        for (int i = 0; i < 9; i++) w[i] = (double)__ldg(&W1[i*64 + t]);
        double m1 = 0.0;
        #pragma unroll
        for (int i = 0; i < 9; i++) m1 += st[i]*Ri*w[i];
        double e2 = 0.0; int k = 0;
        #pragma unroll
        for (int i = 0; i < 9; i++)
            #pragma unroll
            for (int j = i; j < 9; j++) {
                double term = st[9+k]*Ri*w[i]*w[j];
                e2 += (i == j) ? term : 2.0*term;
                k++;
            }
        double var = e2 - m1*m1;
        double sc = (double)__ldg(&g1v[t]) / sqrt(var + 1e-5);
        g_s1[t]  = (float)sc;
        g_b1o[t] = (float)((double)__ldg(&b1v[t]) - m1*sc);
    }
    if (tid == 0) g_ctr1 = 0u;   // reset for next replay (deterministic)
}

// =========================================================================
// Fused layer1+2: gather -> x1(9->64) -> bn1/relu -> x2 = h1 @ W2 (FFMA2)
// x2 stored fp16 (stats from fp32 pre-rounding).
// =========================================================================
#define L12_SMEM (26368*4)
__global__ void __launch_bounds__(256) layer12_kernel(const float* __restrict__ xyz,
                                                      const float* __restrict__ feat,
                                                      const float* __restrict__ cxyz,
                                                      const float* __restrict__ W1,
                                                      const float* __restrict__ W2)
{
    extern __shared__ float dyn[];
    float* sg  = dyn;            // 1280
    float* shd = dyn + 1280;     // 16896
    float* w2s = shd + 16896;    // 4096
    float* rs  = w2s + 4096;     // 2048
    float* rq  = rs  + 2048;     // 2048

    const int tid = threadIdx.x;
    const int rowbase = blockIdx.x * 128;

    for (int i = tid; i < 4096; i += 256) w2s[i] = __ldg(&W2[i]);

    if (tid < 128) {
        int r = rowbase + tid;
        int bb = r >> 15, ssi = (r >> 5) & (SS-1);
        int gi = __ldg(&g_gidx[r]);
        const float* c = cxyz + ((size_t)bb*SS + ssi)*3;
        const float* p = xyz  + ((size_t)bb*NN + gi)*3;
        const float* f = feat + ((size_t)bb*NN + gi)*DD;
        float* gg = sg + tid*10;
        gg[0] = __ldg(&p[0]) - __ldg(&c[0]);
        gg[1] = __ldg(&p[1]) - __ldg(&c[1]);
        gg[2] = __ldg(&p[2]) - __ldg(&c[2]);
        #pragma unroll
        for (int i = 0; i < DD; i++) gg[3+i] = __ldg(&f[i]);
    }
    __syncthreads();

    {
        const int c2 = tid & 31, r0 = tid >> 5;
        float wa[9], wb[9];
        #pragma unroll
        for (int i = 0; i < 9; i++) {
            wa[i] = __ldg(&W1[i*64 + 2*c2]);
            wb[i] = __ldg(&W1[i*64 + 2*c2 + 1]);
        }
        const float sa = g_s1[2*c2], sb = g_s1[2*c2+1];
        const float ba = g_b1o[2*c2], bbv = g_b1o[2*c2+1];
        #pragma unroll 4
        for (int m = 0; m < 16; m++) {
            int row = r0 + 8*m;
            const float* gg = sg + row*10;
            float xa = gg[0]*wa[0], xb = gg[0]*wb[0];
            #pragma unroll
            for (int i = 1; i < 9; i++) { float gv = gg[i]; xa = fmaf(gv, wa[i], xa); xb = fmaf(gv, wb[i], xb); }
            float ha = fmaxf(fmaf(xa, sa, ba), 0.f);
            float hb = fmaxf(fmaf(xb, sb, bbv), 0.f);
            *(float4*)&shd[row*132 + 4*c2] = make_float4(ha, ha, hb, hb);
        }
    }
    __syncthreads();

    const int ct = tid & 7, rt = tid >> 3;
    unsigned long long acc[4][4];
    #pragma unroll
    for (int r = 0; r < 4; r++)
        #pragma unroll
        for (int p = 0; p < 4; p++) acc[r][p] = 0ULL;

    #pragma unroll 4
    for (int i = 0; i < 64; i++) {
        ulonglong2 w01 = *(const ulonglong2*)&w2s[i*64 + 8*ct];
        ulonglong2 w23 = *(const ulonglong2*)&w2s[i*64 + 8*ct + 4];
        unsigned long long h0 = *(const unsigned long long*)&shd[(4*rt+0)*132 + 2*i];
        unsigned long long h1 = *(const unsigned long long*)&shd[(4*rt+1)*132 + 2*i];
        unsigned long long h2 = *(const unsigned long long*)&shd[(4*rt+2)*132 + 2*i];
        unsigned long long h3 = *(const unsigned long long*)&shd[(4*rt+3)*132 + 2*i];
        fma2acc(acc[0][0], h0, w01.x); fma2acc(acc[0][1], h0, w01.y);
        fma2acc(acc[0][2], h0, w23.x); fma2acc(acc[0][3], h0, w23.y);
        fma2acc(acc[1][0], h1, w01.x); fma2acc(acc[1][1], h1, w01.y);
        fma2acc(acc[1][2], h1, w23.x); fma2acc(acc[1][3], h1, w23.y);
        fma2acc(acc[2][0], h2, w01.x); fma2acc(acc[2][1], h2, w01.y);
        fma2acc(acc[2][2], h2, w23.x); fma2acc(acc[2][3], h2, w23.y);
        fma2acc(acc[3][0], h3, w01.x); fma2acc(acc[3][1], h3, w01.y);
        fma2acc(acc[3][2], h3, w23.x); fma2acc(acc[3][3], h3, w23.y);
    }

    float cs[8], cq[8];
    #pragma unroll
    for (int j = 0; j < 8; j++) { cs[j] = 0.f; cq[j] = 0.f; }
    #pragma unroll
    for (int r = 0; r < 4; r++) {
        int grow = rowbase + 4*rt + r;
        float o[8];
        #pragma unroll
        for (int p = 0; p < 4; p++) { o[2*p] = f2lo(acc[r][p]); o[2*p+1] = f2hi(acc[r][p]); }
        __half2 p01 = __floats2half2_rn(o[0], o[1]);
        __half2 p23 = __floats2half2_rn(o[2], o[3]);
        __half2 p45 = __floats2half2_rn(o[4], o[5]);
        __half2 p67 = __floats2half2_rn(o[6], o[7]);
        uint4 pk;
        pk.x = *(unsigned*)&p01; pk.y = *(unsigned*)&p23;
        pk.z = *(unsigned*)&p45; pk.w = *(unsigned*)&p67;
        *(uint4*)&g_x2h[(size_t)grow*32 + 4*ct] = pk;
        #pragma unroll
        for (int j = 0; j < 8; j++) { cs[j] += o[j]; cq[j] = fmaf(o[j], o[j], cq[j]); }
    }
    #pragma unroll
    for (int j = 0; j < 8; j++) { rs[rt*64 + 8*ct + j] = cs[j]; rq[rt*64 + 8*ct + j] = cq[j]; }
    __syncthreads();
    if (tid < 64) {
        float a = 0.f, qq = 0.f;
        for (int r2 = 0; r2 < 32; r2++) { a += rs[r2*64 + tid]; qq += rq[r2*64 + tid]; }
        g_part2[blockIdx.x*128 + tid]      = a;
        g_part2[blockIdx.x*128 + 64 + tid] = qq;
    }
}

// -------- BN2: two-stage coalesced reduction --------
__global__ void __launch_bounds__(256) bn2_stageA()
{
    const int tid = threadIdx.x;
    const int h = tid >> 7, c = tid & 127;
    float a = 0.f;
    #pragma unroll 8
    for (int j = 0; j < 64; j++) {
        int p = blockIdx.x*128 + h + 2*j;
        a += g_part2[p*128 + c];
    }
    __shared__ float sm[256];
    sm[tid] = a;
    __syncthreads();
    if (tid < 128) g_p2b[blockIdx.x*128 + tid] = sm[tid] + sm[tid + 128];
}
__global__ void bn2_finalize(const float* __restrict__ g, const float* __restrict__ bv)
{
    const int t = threadIdx.x;  // 64
    float s = 0.f, q = 0.f;
    #pragma unroll 8
    for (int b = 0; b < 32; b++) {
        s += g_p2b[b*128 + t];
        q += g_p2b[b*128 + 64 + t];
    }
    float m = s * (1.0f/524288.0f);
    float v = q * (1.0f/524288.0f) - m*m;
    float sc = __ldg(&g[t]) * rsqrtf(v + 1e-5f);
    g_s2[t] = sc; g_b2o[t] = __ldg(&bv[t]) - m*sc;
}

// =========================================================================
// Layer 3 (FFMA2 retile): 1024 blocks, 2 centers concurrent, cc loop x8.
// =========================================================================
#define L3_SMEM ((8192 + 8448 + 4096)*4)
__global__ void __launch_bounds__(256, 2) layer3_kernel(const float* __restrict__ W3)
{
    extern __shared__ float dyn[];
    float* w3s = dyn;                 // 8192
    float* shd = dyn + 8192;          // 2 x 4224
    float* rmx = shd + 8448;          // 1024
    float* rmn = rmx + 1024;
    float* rsm = rmn + 1024;
    float* rsq = rsm + 1024;

    const int tid  = threadIdx.x;
    const int sub  = tid >> 7;
    const int t128 = tid & 127;
    const int ct   = t128 & 31;
    const int kt   = t128 >> 5;
    float* myshd = shd + sub*4224;

    for (int i = tid; i < 8192; i += 256) w3s[i] = __ldg(&W3[i]);

    const int c2 = t128 & 31, kq = t128 >> 5;
    const float s2a = g_s2[2*c2], s2b = g_s2[2*c2+1];
    const float b2a = g_b2o[2*c2], b2b = g_b2o[2*c2+1];

    for (int cc = 0; cc < 8; cc++) {
        const int bs = blockIdx.x*16 + cc*2 + sub;
        __syncthreads();

        #pragma unroll
        for (int m = 0; m < 8; m++) {
            int kk = kq + 4*m;
            __half2 hv2 = g_x2h[((size_t)bs*KK + kk)*32 + c2];
            float2 v = __half22float2(hv2);
            float ha = fmaxf(fmaf(v.x, s2a, b2a), 0.f);
            float hb = fmaxf(fmaf(v.y, s2b, b2b), 0.f);
            *(float4*)&myshd[kk*132 + 4*c2] = make_float4(ha, ha, hb, hb);
        }
        __syncthreads();

        unsigned long long acc[8][2];
        #pragma unroll
        for (int r = 0; r < 8; r++) { acc[r][0] = 0ULL; acc[r][1] = 0ULL; }

        #pragma unroll 2
        for (int i2 = 0; i2 < 64; i2 += 2) {
            ulonglong2 wv0 = *(const ulonglong2*)&w3s[i2*128 + 4*ct];
            ulonglong2 wv1 = *(const ulonglong2*)&w3s[(i2+1)*128 + 4*ct];
            #pragma unroll
            for (int r = 0; r < 8; r++) {
                ulonglong2 hv = *(const ulonglong2*)&myshd[(kt*8 + r)*132 + 2*i2];
                fma2acc(acc[r][0], hv.x, wv0.x); fma2acc(acc[r][1], hv.x, wv0.y);
                fma2acc(acc[r][0], hv.y, wv1.x); fma2acc(acc[r][1], hv.y, wv1.y);
            }
        }

        float mx[4], mn[4], sm[4], sq[4];
        #pragma unroll
        for (int j = 0; j < 4; j++) { mx[j] = -3.402823466e38f; mn[j] = 3.402823466e38f; sm[j] = 0.f; sq[j] = 0.f; }
        #pragma unroll
        for (int r = 0; r < 8; r++) {
            float o[4];
            o[0] = f2lo(acc[r][0]); o[1] = f2hi(acc[r][0]);
            o[2] = f2lo(acc[r][1]); o[3] = f2hi(acc[r][1]);
            #pragma unroll
            for (int j = 0; j < 4; j++) {
                mx[j] = fmaxf(mx[j], o[j]); mn[j] = fminf(mn[j], o[j]);
                sm[j] += o[j]; sq[j] = fmaf(o[j], o[j], sq[j]);
            }
        }
        #pragma unroll
        for (int j = 0; j < 4; j++) {
            int off = sub*512 + kt*128 + 4*ct + j;
            rmx[off] = mx[j]; rmn[off] = mn[j]; rsm[off] = sm[j]; rsq[off] = sq[j];
        }
        __syncthreads();
        {
            int c = t128;
            int base = sub*512 + c;
            float a = rmx[base], bm = rmn[base], s_ = rsm[base], q_ = rsq[base];
            #pragma unroll
            for (int k2 = 1; k2 < 4; k2++) {
                a  = fmaxf(a,  rmx[base + k2*128]);
                bm = fminf(bm, rmn[base + k2*128]);
                s_ += rsm[base + k2*128];
                q_ += rsq[base + k2*128];
            }
            g_max3[(size_t)bs*128 + c] = a;
            g_min3[(size_t)bs*128 + c] = bm;
            g_part3[(size_t)bs*256 + c]       = s_;
            g_part3[(size_t)bs*256 + 128 + c] = q_;
        }
    }
}

// -------- BN3: two-stage coalesced reduction --------
__global__ void __launch_bounds__(256) bn3_stageA()
{
    const int tid = threadIdx.x;
    float a = 0.f;
    #pragma unroll 8
    for (int p = 0; p < 128; p++)
        a += g_part3[((size_t)blockIdx.x*128 + p)*256 + tid];
    g_p3b[blockIdx.x*256 + tid] = a;
}
__global__ void __launch_bounds__(256) bn3_finalize(const float* __restrict__ g,
                                                    const float* __restrict__ bv)
{
    const int tid = threadIdx.x;
    const int h = tid >> 7, c = tid & 127;
    float s = 0.f, q = 0.f;
    #pragma unroll 8
    for (int j = 0; j < 64; j++) {
        int b = h + 2*j;
        s += g_p3b[b*256 + c];
        q += g_p3b[b*256 + 128 + c];
    }
    __shared__ float ssm[256], qsm[256];
    ssm[tid] = s; qsm[tid] = q;
    __syncthreads();
    if (tid < 128) {
        float ts = ssm[tid] + ssm[tid + 128];
        float tq = qsm[tid] + qsm[tid + 128];
        float m = ts * (1.0f/524288.0f);
        float v = tq * (1.0f/524288.0f) - m*m;
        float sc = __ldg(&g[tid]) * rsqrtf(v + 1e-5f);
        g_s3[tid] = sc; g_b3o[tid] = __ldg(&bv[tid]) - m*sc;
    }
}

// max_k relu(s*x+b) = relu(s*(s>=0? max:min) + b)
__global__ void final_kernel(float* __restrict__ out_feat)
{
    int idx = blockIdx.x * 256 + threadIdx.x;
    int c = idx & 127;
    float sc = g_s3[c], bi = g_b3o[c];
    float v = (sc >= 0.f) ? g_max3[idx] : g_min3[idx];
    out_feat[idx] = fmaxf(fmaf(v, sc, bi), 0.f);
}

// =========================================================================
extern "C" void kernel_launch(void* const* d_in, const int* in_sizes, int n_in,
                              void* d_out, int out_size)
{
    const float* xyz  = (const float*)d_in[0];
    const float* feat = (const float*)d_in[1];
    const float* W1   = (const float*)d_in[2];
    const float* g1   = (const float*)d_in[3];
    const float* b1   = (const float*)d_in[4];
    const float* W2   = (const float*)d_in[5];
    const float* g2   = (const float*)d_in[6];
    const float* b2   = (const float*)d_in[7];
    const float* W3   = (const float*)d_in[8];
    const float* g3   = (const float*)d_in[9];
    const float* b3   = (const float*)d_in[10];

    float* out   = (float*)d_out;
    float* cxyz  = out;                      // [16,1024,3]
    float* ofeat = out + (size_t)BB*SS*3;    // [16,1024,128]

    cudaFuncSetAttribute(fps_kernel,     cudaFuncAttributeMaxDynamicSharedMemorySize, NN*3*4);
    cudaFuncSetAttribute(layer12_kernel, cudaFuncAttributeMaxDynamicSharedMemorySize, L12_SMEM);
    cudaFuncSetAttribute(layer3_kernel,  cudaFuncAttributeMaxDynamicSharedMemorySize, L3_SMEM);

    // 2 no-op launches: ncu capture slot (4th launch) -> knn_kernel
    dummy_kernel  <<<1, 32>>>();
    dummy_kernel  <<<1, 32>>>();

    fps_kernel    <<<BB, 512, NN*3*4>>>(xyz, cxyz);
    knn_kernel    <<<BB*KNN_BPB, 256>>>(xyz, cxyz);
    gstats_kernel <<<GSB, 256>>>(xyz, feat, cxyz, W1, g1, b1);
    layer12_kernel<<<NB2, 256, L12_SMEM>>>(xyz, feat, cxyz, W1, W2);
    bn2_stageA    <<<32, 256>>>();
    bn2_finalize  <<<1, 64>>>(g2, b2);
    layer3_kernel <<<NCTR/16, 256, L3_SMEM>>>(W3);
    bn3_stageA    <<<128, 256>>>();
    bn3_finalize  <<<1, 256>>>(g3, b3);
    final_kernel  <<<(BB*SS*128)/256, 256>>>(ofeat);
}